// round 12
// baseline (speedup 1.0000x reference)
#include <cuda_runtime.h>
#include <cuda_bf16.h>
#include <cuda_fp16.h>
#include <cstdint>

#define NQ      16384
#define NKV     32768
#define DEC     64
#define NF      128
#define NBATCH  8
#define NQB     2048
#define NKB     4096
#define BN_EPS  1e-4f

// ---------------- scratch (alloc-free: device globals) ----------------
__device__ float g_xdec[NQ * NF];
__device__ float g_t   [NQ * NF];
__device__ float g_psum[(NQ / 64) * NF];
__device__ float g_psq [(NQ / 64) * NF];
__device__ float g_mean[NF];
__device__ float g_rstd[NF];
__device__ __nv_bfloat16 g_dfh[NQ * DEC],  g_dfl[NQ * DEC];
__device__ __nv_bfloat16 g_eh [NKV * DEC], g_el [NKV * DEC];
__device__ __nv_bfloat16 g_wp1h[27 * 64 * 128], g_wp1l[27 * 64 * 128];
__device__ __nv_bfloat16 g_wkh[64 * 128],  g_wkl[64 * 128];
__device__ __nv_bfloat16 g_wvh[64 * 128],  g_wvl[64 * 128];
__device__ __nv_bfloat16 g_wqh[128 * 128], g_wql[128 * 128];
__device__ __nv_bfloat16 g_wth[128 * 128], g_wtl[128 * 128];
__device__ __nv_bfloat16 g_xdh[NQ * NF],  g_xdl[NQ * NF];
__device__ __nv_bfloat16 g_qh[NQ * NF],   g_ql[NQ * NF];
__device__ __nv_bfloat16 g_kh[NKV * NF],  g_kl[NKV * NF];
__device__ __half        g_vh[NKV * NF],  g_vl[NKV * NF];
__device__ __nv_bfloat16 g_xrh[NQ * NF],  g_xrl[NQ * NF];

// ---------------- helpers ----------------
__device__ __forceinline__ uint32_t packb(__nv_bfloat16 x, __nv_bfloat16 y) {
    __nv_bfloat162 v(x, y);
    return *reinterpret_cast<uint32_t*>(&v);
}
__device__ __forceinline__ void split2(float a, float b, uint32_t& hi, uint32_t& lo) {
    __nv_bfloat16 ah = __float2bfloat16(a);
    __nv_bfloat16 bh = __float2bfloat16(b);
    float ar = a - __bfloat162float(ah);
    float br = b - __bfloat162float(bh);
    hi = packb(ah, bh);
    lo = packb(__float2bfloat16(ar), __float2bfloat16(br));
}
__device__ __forceinline__ uint32_t packh(float a, float b) {
    __half2 h = __floats2half2_rn(a, b);
    return *reinterpret_cast<uint32_t*>(&h);
}
__device__ __forceinline__ void mma16816(float* d, const uint32_t* a, const uint32_t* b) {
    asm volatile("mma.sync.aligned.m16n8k16.row.col.f32.bf16.bf16.f32 "
                 "{%0,%1,%2,%3}, {%4,%5,%6,%7}, {%8,%9}, {%0,%1,%2,%3};"
                 : "+f"(d[0]), "+f"(d[1]), "+f"(d[2]), "+f"(d[3])
                 : "r"(a[0]), "r"(a[1]), "r"(a[2]), "r"(a[3]), "r"(b[0]), "r"(b[1]));
}
__device__ __forceinline__ void mma16816h(float* d, const uint32_t* a, const uint32_t* b) {
    asm volatile("mma.sync.aligned.m16n8k16.row.col.f32.f16.f16.f32 "
                 "{%0,%1,%2,%3}, {%4,%5,%6,%7}, {%8,%9}, {%0,%1,%2,%3};"
                 : "+f"(d[0]), "+f"(d[1]), "+f"(d[2]), "+f"(d[3])
                 : "r"(a[0]), "r"(a[1]), "r"(a[2]), "r"(a[3]), "r"(b[0]), "r"(b[1]));
}
__device__ __forceinline__ void ldsm4(uint32_t* r, uint32_t addr) {
    asm volatile("ldmatrix.sync.aligned.m8n8.x4.shared.b16 {%0,%1,%2,%3}, [%4];"
                 : "=r"(r[0]), "=r"(r[1]), "=r"(r[2]), "=r"(r[3]) : "r"(addr));
}
__device__ __forceinline__ void ldsm4t(uint32_t* r, uint32_t addr) {
    asm volatile("ldmatrix.sync.aligned.m8n8.x4.trans.shared.b16 {%0,%1,%2,%3}, [%4];"
                 : "=r"(r[0]), "=r"(r[1]), "=r"(r[2]), "=r"(r[3]) : "r"(addr));
}
__device__ __forceinline__ void cpa16(uint32_t dst, const void* src) {
    asm volatile("cp.async.cg.shared.global [%0], [%1], 16;" :: "r"(dst), "l"(src));
}
__device__ __forceinline__ void cpa_commit() {
    asm volatile("cp.async.commit_group;");
}

// ======================================================================
// Split-prep
// ======================================================================
#define SB0 (NQ * DEC)
#define SB1 (SB0 + NKV * DEC)
#define SB2 (SB1 + 27 * 64 * 128)
#define SB3 (SB2 + 64 * 128)
#define SB4 (SB3 + 64 * 128)
#define SB5 (SB4 + 128 * 128)
#define SB6 (SB5 + 128 * 128)

__device__ __forceinline__ void split4(float4 v, uint2& h, uint2& l) {
    uint32_t h0, l0, h1, l1;
    split2(v.x, v.y, h0, l0);
    split2(v.z, v.w, h1, l1);
    h = {h0, h1};
    l = {l0, l1};
}

__global__ void k_split7(const float* __restrict__ xdf, const float* __restrict__ xef,
                         const float* __restrict__ Wp1, const float* __restrict__ Wk,
                         const float* __restrict__ Wv,  const float* __restrict__ Wq,
                         const float* __restrict__ Wt)
{
    int e = (blockIdx.x * 256 + threadIdx.x) * 4;
    const float* src; __nv_bfloat16 *dh, *dl; int off;
    if      (e < SB0) { src = xdf; dh = g_dfh;  dl = g_dfl;  off = e; }
    else if (e < SB1) { src = xef; dh = g_eh;   dl = g_el;   off = e - SB0; }
    else if (e < SB2) { src = Wp1; dh = g_wp1h; dl = g_wp1l; off = e - SB1; }
    else if (e < SB3) { src = Wk;  dh = g_wkh;  dl = g_wkl;  off = e - SB2; }
    else if (e < SB4) { src = Wv;  dh = g_wvh;  dl = g_wvl;  off = e - SB3; }
    else if (e < SB5) { src = Wq;  dh = g_wqh;  dl = g_wql;  off = e - SB4; }
    else              { src = Wt;  dh = g_wth;  dl = g_wtl;  off = e - SB5; }
    float4 v = *reinterpret_cast<const float4*>(src + off);
    uint2 h, l;
    split4(v, h, l);
    *reinterpret_cast<uint2*>(dh + off) = h;
    *reinterpret_cast<uint2*>(dl + off) = l;
}

// ======================================================================
// Shared HMMA tile machinery (64x128 tile, 8 warps as 4 qw x 2 nw)
// ======================================================================
#define GOAH  0
#define GOAL  9216
#define GOBH  18432
#define GOBL  35840
#define GSTG  53248
#define GSMSZ (GSTG + 4096)

__device__ __forceinline__ void mma_tile64(uint32_t sbase,
                                           uint32_t bOffH, uint32_t bOffL,
                                           int qw, int nw, int lane,
                                           float acc[8][4])
{
    const int rA = lane & 15, cA = (lane >> 4) * 8;
    const int rV = ((lane >> 3) & 1) * 8 + (lane & 7);
    const int cV = ((lane >> 3) & 2) * 4;
#pragma unroll
    for (int kc = 0; kc < 4; ++kc) {
        uint32_t Aaddr = sbase + (uint32_t)((qw * 16 + rA) * 72 + kc * 16 + cA) * 2;
        uint32_t Ah4[4], Al4[4];
        ldsm4(Ah4, Aaddr + GOAH);
        ldsm4(Al4, Aaddr + GOAL);
#pragma unroll
        for (int nt2 = 0; nt2 < 4; ++nt2) {
            uint32_t ra = (uint32_t)((kc * 16 + rV) * 136 + nw * 64 + nt2 * 16 + cV) * 2;
            uint32_t Bh4[4], Bl4[4];
            ldsm4t(Bh4, sbase + bOffH + ra);
            ldsm4t(Bl4, sbase + bOffL + ra);
            float* a0 = acc[nt2 * 2];
            float* a1 = acc[nt2 * 2 + 1];
            mma16816(a0, Ah4, Bh4);  mma16816(a1, Ah4, Bh4 + 2);
            mma16816(a0, Ah4, Bl4);  mma16816(a1, Ah4, Bl4 + 2);
            mma16816(a0, Al4, Bh4);  mma16816(a1, Al4, Bh4 + 2);
        }
    }
}

// ======================================================================
// p1 gather-conv (unchanged winner)
// ======================================================================
__global__ __launch_bounds__(256) void k_p1_mma(const int* __restrict__ nbr)
{
    extern __shared__ char smr[];
    const uint32_t sbase = (uint32_t)__cvta_generic_to_shared(smr);
    const int tid = threadIdx.x;
    const int wid = tid >> 5, lane = tid & 31;
    const int qw = wid >> 1, nw = wid & 1;
    const int m0 = blockIdx.x * 64;

    float acc[8][4];
#pragma unroll
    for (int i = 0; i < 8; ++i)
#pragma unroll
        for (int j = 0; j < 4; ++j) acc[i][j] = 0.f;

    auto prefetch = [&](int k, int s) {
        uint32_t sb = sbase + s * GSTG;
#pragma unroll
        for (int i = 0; i < 2; ++i) {
            int idx = tid + i * 256;
            int r = idx >> 3, c = idx & 7;
            int gi = nbr[(m0 + r) * 27 + k];
            uint32_t so = (uint32_t)(r * 72 + c * 8) * 2;
            cpa16(sb + GOAH + so, g_dfh + (size_t)gi * DEC + c * 8);
            cpa16(sb + GOAL + so, g_dfl + (size_t)gi * DEC + c * 8);
        }
        const __nv_bfloat16* wh = g_wp1h + (size_t)k * 64 * 128;
        const __nv_bfloat16* wl = g_wp1l + (size_t)k * 64 * 128;
#pragma unroll
        for (int i = 0; i < 4; ++i) {
            int idx = tid + i * 256;
            int r = idx >> 4, c = idx & 15;
            uint32_t so = (uint32_t)(r * 136 + c * 8) * 2;
            cpa16(sb + GOBH + so, wh + r * 128 + c * 8);
            cpa16(sb + GOBL + so, wl + r * 128 + c * 8);
        }
        cpa_commit();
    };

    prefetch(0, 0);
    for (int k = 0; k < 27; ++k) {
        const int s = k & 1;
        if (k + 1 < 27) {
            prefetch(k + 1, s ^ 1);
            asm volatile("cp.async.wait_group 1;");
        } else {
            asm volatile("cp.async.wait_group 0;");
        }
        __syncthreads();
        mma_tile64(sbase + s * GSTG, GOBH, GOBL, qw, nw, lane, acc);
        __syncthreads();
    }

    const int g = lane >> 2, t = lane & 3;
    const int r0 = m0 + qw * 16 + g, r1 = r0 + 8;
#pragma unroll
    for (int nt = 0; nt < 8; ++nt) {
        int col = nw * 64 + nt * 8 + 2 * t;
        float2 v0 = {acc[nt][0], acc[nt][1]};
        float2 v1 = {acc[nt][2], acc[nt][3]};
        *reinterpret_cast<float2*>(g_xdec + (size_t)r0 * 128 + col) = v0;
        *reinterpret_cast<float2*>(g_xdec + (size_t)r1 * 128 + col) = v1;
        uint32_t h, l;
        split2(v0.x, v0.y, h, l);
        *reinterpret_cast<uint32_t*>(g_xdh + (size_t)r0 * 128 + col) = h;
        *reinterpret_cast<uint32_t*>(g_xdl + (size_t)r0 * 128 + col) = l;
        split2(v1.x, v1.y, h, l);
        *reinterpret_cast<uint32_t*>(g_xdh + (size_t)r1 * 128 + col) = h;
        *reinterpret_cast<uint32_t*>(g_xdl + (size_t)r1 * 128 + col) = l;
    }
}

// ======================================================================
// Fused K+V projection: K split-bf16, V split-fp16
// ======================================================================
#define KV_BKH 18432
#define KV_BKL (KV_BKH + 17408)
#define KV_BVH (KV_BKH + 34816)
#define KV_BVL (KV_BVH + 17408)
#define KVSMSZ (KV_BVH + 34816)

__global__ __launch_bounds__(256) void k_projKV()
{
    extern __shared__ char smr[];
    const uint32_t sbase = (uint32_t)__cvta_generic_to_shared(smr);
    const int tid = threadIdx.x;
    const int wid = tid >> 5, lane = tid & 31;
    const int qw = wid >> 1, nw = wid & 1;
    const int m0 = blockIdx.x * 64;

#pragma unroll
    for (int i = 0; i < 2; ++i) {
        int idx = tid + i * 256;
        int r = idx >> 3, c = idx & 7;
        size_t go = (size_t)(m0 + r) * DEC + c * 8;
        uint32_t so = (uint32_t)(r * 72 + c * 8) * 2;
        cpa16(sbase + GOAH + so, g_eh + go);
        cpa16(sbase + GOAL + so, g_el + go);
    }
#pragma unroll
    for (int i = 0; i < 4; ++i) {
        int idx = tid + i * 256;
        int r = idx >> 4, c = idx & 15;
        size_t go = (size_t)r * 128 + c * 8;
        uint32_t so = (uint32_t)(r * 136 + c * 8) * 2;
        cpa16(sbase + KV_BKH + so, g_wkh + go);
        cpa16(sbase + KV_BKL + so, g_wkl + go);
        cpa16(sbase + KV_BVH + so, g_wvh + go);
        cpa16(sbase + KV_BVL + so, g_wvl + go);
    }
    cpa_commit();
    asm volatile("cp.async.wait_group 0;");
    __syncthreads();

    float accK[8][4], accV[8][4];
#pragma unroll
    for (int i = 0; i < 8; ++i)
#pragma unroll
        for (int j = 0; j < 4; ++j) { accK[i][j] = 0.f; accV[i][j] = 0.f; }

    mma_tile64(sbase, KV_BKH, KV_BKL, qw, nw, lane, accK);
    mma_tile64(sbase, KV_BVH, KV_BVL, qw, nw, lane, accV);

    const int g = lane >> 2, t = lane & 3;
    const int r0 = m0 + qw * 16 + g, r1 = r0 + 8;
#pragma unroll
    for (int nt = 0; nt < 8; ++nt) {
        int col = nw * 64 + nt * 8 + 2 * t;
        uint32_t h, l;
        split2(accK[nt][0], accK[nt][1], h, l);
        *reinterpret_cast<uint32_t*>(g_kh + (size_t)r0 * 128 + col) = h;
        *reinterpret_cast<uint32_t*>(g_kl + (size_t)r0 * 128 + col) = l;
        split2(accK[nt][2], accK[nt][3], h, l);
        *reinterpret_cast<uint32_t*>(g_kh + (size_t)r1 * 128 + col) = h;
        *reinterpret_cast<uint32_t*>(g_kl + (size_t)r1 * 128 + col) = l;
#pragma unroll
        for (int cc = 0; cc < 2; ++cc) {
            float v0 = accV[nt][cc];
            float v1 = accV[nt][2 + cc];
            __half h0 = __float2half_rn(v0);
            g_vh[(size_t)r0 * 128 + col + cc] = h0;
            g_vl[(size_t)r0 * 128 + col + cc] = __float2half_rn(v0 - __half2float(h0));
            __half h1 = __float2half_rn(v1);
            g_vh[(size_t)r1 * 128 + col + cc] = h1;
            g_vl[(size_t)r1 * 128 + col + cc] = __float2half_rn(v1 - __half2float(h1));
        }
    }
}

// ======================================================================
// Generic split-bf16 HMMA GEMM (+ split out / BN stats) — unchanged winner
// ======================================================================
template <int KA, bool SPLIT, bool STATS>
__global__ __launch_bounds__(256) void k_proj(const __nv_bfloat16* __restrict__ Ahg,
                                              const __nv_bfloat16* __restrict__ Alg,
                                              const __nv_bfloat16* __restrict__ Bhg,
                                              const __nv_bfloat16* __restrict__ Blg,
                                              __nv_bfloat16* __restrict__ Ch,
                                              __nv_bfloat16* __restrict__ Cl,
                                              float* __restrict__ Cf)
{
    extern __shared__ char smr[];
    const uint32_t sbase = (uint32_t)__cvta_generic_to_shared(smr);
    const int tid = threadIdx.x;
    const int wid = tid >> 5, lane = tid & 31;
    const int qw = wid >> 1, nw = wid & 1;
    const int m0 = blockIdx.x * 64;

    float acc[8][4];
#pragma unroll
    for (int i = 0; i < 8; ++i)
#pragma unroll
        for (int j = 0; j < 4; ++j) acc[i][j] = 0.f;

#pragma unroll
    for (int kb = 0; kb < KA / 64; ++kb) {
        __syncthreads();
#pragma unroll
        for (int i = 0; i < 2; ++i) {
            int idx = tid + i * 256;
            int r = idx >> 3, c = idx & 7;
            size_t go = (size_t)(m0 + r) * KA + kb * 64 + c * 8;
            uint32_t so = (uint32_t)(r * 72 + c * 8) * 2;
            cpa16(sbase + GOAH + so, Ahg + go);
            cpa16(sbase + GOAL + so, Alg + go);
        }
#pragma unroll
        for (int i = 0; i < 4; ++i) {
            int idx = tid + i * 256;
            int r = idx >> 4, c = idx & 15;
            size_t go = (size_t)(kb * 64 + r) * 128 + c * 8;
            uint32_t so = (uint32_t)(r * 136 + c * 8) * 2;
            cpa16(sbase + GOBH + so, Bhg + go);
            cpa16(sbase + GOBL + so, Blg + go);
        }
        cpa_commit();
        asm volatile("cp.async.wait_group 0;");
        __syncthreads();
        mma_tile64(sbase, GOBH, GOBL, qw, nw, lane, acc);
    }

    const int g = lane >> 2, t = lane & 3;
    const int r0 = m0 + qw * 16 + g, r1 = r0 + 8;
#pragma unroll
    for (int nt = 0; nt < 8; ++nt) {
        int col = nw * 64 + nt * 8 + 2 * t;
        if (SPLIT) {
            uint32_t h, l;
            split2(acc[nt][0], acc[nt][1], h, l);
            *reinterpret_cast<uint32_t*>(Ch + (size_t)r0 * 128 + col) = h;
            *reinterpret_cast<uint32_t*>(Cl + (size_t)r0 * 128 + col) = l;
            split2(acc[nt][2], acc[nt][3], h, l);
            *reinterpret_cast<uint32_t*>(Ch + (size_t)r1 * 128 + col) = h;
            *reinterpret_cast<uint32_t*>(Cl + (size_t)r1 * 128 + col) = l;
        } else {
            float2 v0 = {acc[nt][0], acc[nt][1]};
            float2 v1 = {acc[nt][2], acc[nt][3]};
            *reinterpret_cast<float2*>(Cf + (size_t)r0 * 128 + col) = v0;
            *reinterpret_cast<float2*>(Cf + (size_t)r1 * 128 + col) = v1;
        }
    }

    if (STATS) {
        float* sS = reinterpret_cast<float*>(smr);
        float* sQ = reinterpret_cast<float*>(smr + 2048);
        __syncthreads();
        float cs[8][2], cq[8][2];
#pragma unroll
        for (int nt = 0; nt < 8; ++nt) {
            cs[nt][0] = acc[nt][0] + acc[nt][2];
            cs[nt][1] = acc[nt][1] + acc[nt][3];
            cq[nt][0] = acc[nt][0] * acc[nt][0] + acc[nt][2] * acc[nt][2];
            cq[nt][1] = acc[nt][1] * acc[nt][1] + acc[nt][3] * acc[nt][3];
        }
#pragma unroll
        for (int off = 4; off < 32; off <<= 1) {
#pragma unroll
            for (int nt = 0; nt < 8; ++nt) {
                cs[nt][0] += __shfl_xor_sync(0xffffffffu, cs[nt][0], off);
                cs[nt][1] += __shfl_xor_sync(0xffffffffu, cs[nt][1], off);
                cq[nt][0] += __shfl_xor_sync(0xffffffffu, cq[nt][0], off);
                cq[nt][1] += __shfl_xor_sync(0xffffffffu, cq[nt][1], off);
            }
        }
        if (lane < 4) {
#pragma unroll
            for (int nt = 0; nt < 8; ++nt) {
                int col = nw * 64 + nt * 8 + 2 * lane;
                sS[qw * 128 + col]     = cs[nt][0];
                sS[qw * 128 + col + 1] = cs[nt][1];
                sQ[qw * 128 + col]     = cq[nt][0];
                sQ[qw * 128 + col + 1] = cq[nt][1];
            }
        }
        __syncthreads();
        if (tid < 128) {
            float s = sS[tid] + sS[128 + tid] + sS[256 + tid] + sS[384 + tid];
            float q = sQ[tid] + sQ[128 + tid] + sQ[256 + tid] + sQ[384 + tid];
            g_psum[blockIdx.x * 128 + tid] = s;
            g_psq [blockIdx.x * 128 + tid] = q;
        }
    }
}

// ======================================================================
// Flash attention (round-9 winner, exact): 128 q-rows/block, 256 threads,
// kv-tile 64 as two interleaved 32-halves, warp-private softmax, Q in
// regs, cp.async double-buffered, PV fp16 2-term, unconditional rescale.
// ======================================================================
#define STG   17408
#define SSTAGE (4 * STG)
#define ASMSZ2 (2 * SSTAGE)

__global__ __launch_bounds__(256, 1) void k_attn()
{
    extern __shared__ char smr[];
    const uint32_t sbase = (uint32_t)__cvta_generic_to_shared(smr);

    const int tid  = threadIdx.x;
    const int w    = tid >> 5, lane = tid & 31;
    const int g    = lane >> 2, t = lane & 3;
    const int b    = blockIdx.y;
    const size_t qrow0 = (size_t)b * NQB + blockIdx.x * 128;

    const int rA = lane & 15;
    const int cA = (lane >> 4) * 8;
    const int rB = ((lane >> 3) & 2) * 4 + (lane & 7);
    const int cB = ((lane >> 3) & 1) * 8;
    const int rV = ((lane >> 3) & 1) * 8 + (lane & 7);
    const int cV = ((lane >> 3) & 2) * 4;

    // ---- stage Q, load register A-fragments ----
    uint32_t Qh[8][4], Ql[8][4];
    {
        const __nv_bfloat16* qh = g_qh + qrow0 * 128;
        const __nv_bfloat16* ql = g_ql + qrow0 * 128;
#pragma unroll
        for (int i = 0; i < 8; ++i) {
            int idx = tid + i * 256;
            int r = idx >> 4, c = idx & 15;
            uint32_t so = (uint32_t)(r * 136 + c * 8) * 2;
            cpa16(sbase + so,         qh + (size_t)r * 128 + c * 8);
            cpa16(sbase + 34816 + so, ql + (size_t)r * 128 + c * 8);
        }
        cpa_commit();
        asm volatile("cp.async.wait_group 0;");
        __syncthreads();
#pragma unroll
        for (int ch = 0; ch < 8; ++ch) {
            uint32_t Aaddr = sbase + (uint32_t)((w * 16 + rA) * 136 + ch * 16 + cA) * 2;
            ldsm4(Qh[ch], Aaddr);
            ldsm4(Ql[ch], Aaddr + 34816);
        }
        __syncthreads();
    }

    float O[16][4];
#pragma unroll
    for (int i = 0; i < 16; ++i)
#pragma unroll
        for (int j = 0; j < 4; ++j) O[i][j] = 0.f;
    float m0r = -1e30f, m1r = -1e30f, l0 = 0.f, l1 = 0.f;

    const size_t kvbase = (size_t)b * NKB * 128;
    auto prefetch = [&](int jt, int s) {
        size_t base = kvbase + (size_t)jt * 64 * 128;
        uint32_t sb = sbase + s * SSTAGE;
#pragma unroll
        for (int i = 0; i < 16; ++i) {
            int arr = i >> 2;
            int idx = tid + (i & 3) * 256;
            int r = idx >> 4, c = idx & 15;
            uint32_t so = sb + arr * STG + (uint32_t)(r * 136 + c * 8) * 2;
            size_t eo = base + (size_t)r * 128 + c * 8;
            const void* src;
            if      (arr == 0) src = g_kh + eo;
            else if (arr == 1) src = g_kl + eo;
            else if (arr == 2) src = g_vh + eo;
            else               src = g_vl + eo;
            cpa16(so, src);
        }
        cpa_commit();
    };

    prefetch(0, 0);

    const int NIT = NKB / 64;
    for (int jt = 0; jt < NIT; ++jt) {
        const int s = jt & 1;
        if (jt + 1 < NIT) {
            prefetch(jt + 1, s ^ 1);
            asm volatile("cp.async.wait_group 1;");
        } else {
            asm volatile("cp.async.wait_group 0;");
        }
        __syncthreads();

        const uint32_t KHb = sbase + s * SSTAGE;
        const uint32_t KLb = KHb + STG;
        const uint32_t VHb = KHb + 2 * STG;
        const uint32_t VLb = KHb + 3 * STG;

        // ---- S for BOTH halves (back-to-back MMA issue) ----
        float sA[8][4];
#pragma unroll
        for (int i = 0; i < 8; ++i)
#pragma unroll
            for (int j = 0; j < 4; ++j) sA[i][j] = 0.f;

#pragma unroll
        for (int half = 0; half < 2; ++half) {
#pragma unroll
            for (int ch = 0; ch < 8; ++ch) {
                uint32_t col = (uint32_t)(ch * 16 + cB) * 2;
#pragma unroll
                for (int r4h = 0; r4h < 2; ++r4h) {
                    int r4 = half * 2 + r4h;
                    uint32_t ra = (uint32_t)((r4 * 16 + rB) * 136) * 2 + col;
                    uint32_t bh[4], bl[4];
                    ldsm4(bh, KHb + ra);
                    ldsm4(bl, KLb + ra);
                    float* s0 = sA[r4 * 2];
                    float* s1 = sA[r4 * 2 + 1];
                    mma16816(s0, Qh[ch], bh);      mma16816(s1, Qh[ch], bh + 2);
                    mma16816(s0, Qh[ch], bl);      mma16816(s1, Qh[ch], bl + 2);
                    mma16816(s0, Ql[ch], bh);      mma16816(s1, Ql[ch], bh + 2);
                }
            }
        }

        // ---- per-half softmax + PV (unconditional rescale, straight-line) ----
#pragma unroll
        for (int half = 0; half < 2; ++half) {
            float (*sH)[4] = &sA[half * 4];

            float rm0 = sH[0][0], rm1 = sH[0][2];
#pragma unroll
            for (int nt = 0; nt < 4; ++nt) {
                rm0 = fmaxf(rm0, fmaxf(sH[nt][0], sH[nt][1]));
                rm1 = fmaxf(rm1, fmaxf(sH[nt][2], sH[nt][3]));
            }
            rm0 = fmaxf(rm0, __shfl_xor_sync(0xffffffffu, rm0, 1));
            rm0 = fmaxf(rm0, __shfl_xor_sync(0xffffffffu, rm0, 2));
            rm1 = fmaxf(rm1, __shfl_xor_sync(0xffffffffu, rm1, 1));
            rm1 = fmaxf(rm1, __shfl_xor_sync(0xffffffffu, rm1, 2));
            float mn0 = fmaxf(m0r, rm0);
            float mn1 = fmaxf(m1r, rm1);
            float sc0 = __expf(m0r - mn0);
            float sc1 = __expf(m1r - mn1);

            float p[4][4];
            float ls0 = 0.f, ls1 = 0.f;
#pragma unroll
            for (int nt = 0; nt < 4; ++nt) {
                p[nt][0] = __expf(sH[nt][0] - mn0);
                p[nt][1] = __expf(sH[nt][1] - mn0);
                p[nt][2] = __expf(sH[nt][2] - mn1);
                p[nt][3] = __expf(sH[nt][3] - mn1);
                ls0 += p[nt][0] + p[nt][1];
                ls1 += p[nt][2] + p[nt][3];
            }
            ls0 += __shfl_xor_sync(0xffffffffu, ls0, 1);
            ls0 += __shfl_xor_sync(0xffffffffu, ls0, 2);
            ls1 += __shfl_xor_sync(0xffffffffu, ls1, 1);
            ls1 += __shfl_xor_sync(0xffffffffu, ls1, 2);
            l0 = l0 * sc0 + ls0;
            l1 = l1 * sc1 + ls1;
            m0r = mn0; m1r = mn1;

#pragma unroll
            for (int nt = 0; nt < 16; ++nt) {
                O[nt][0] *= sc0; O[nt][1] *= sc0;
                O[nt][2] *= sc1; O[nt][3] *= sc1;
            }

            // P as plain fp16 A-fragments (2 k-chunks of 16 per half)
            uint32_t Ph[2][4];
#pragma unroll
            for (int c = 0; c < 2; ++c) {
                Ph[c][0] = packh(p[2 * c][0],     p[2 * c][1]);
                Ph[c][1] = packh(p[2 * c][2],     p[2 * c][3]);
                Ph[c][2] = packh(p[2 * c + 1][0], p[2 * c + 1][1]);
                Ph[c][3] = packh(p[2 * c + 1][2], p[2 * c + 1][3]);
            }

            // O += P(fp16) * (Vh + Vl)(fp16)
#pragma unroll
            for (int kcl = 0; kcl < 2; ++kcl) {
                int kc = half * 2 + kcl;
#pragma unroll
                for (int dp = 0; dp < 8; ++dp) {
                    uint32_t ra = (uint32_t)((kc * 16 + rV) * 136 + dp * 16 + cV) * 2;
                    uint32_t vh[4], vl[4];
                    ldsm4t(vh, VHb + ra);
                    ldsm4t(vl, VLb + ra);
                    float* o0 = O[dp * 2];
                    float* o1 = O[dp * 2 + 1];
                    mma16816h(o0, Ph[kcl], vh);    mma16816h(o1, Ph[kcl], vh + 2);
                    mma16816h(o0, Ph[kcl], vl);    mma16816h(o1, Ph[kcl], vl + 2);
                }
            }
        }
        __syncthreads();
    }

    // ---- epilogue: normalize, split, store ----
    float inv0 = 1.f / l0, inv1 = 1.f / l1;
    size_t out0 = (qrow0 + w * 16 + g) * 128;
    size_t out1 = (qrow0 + w * 16 + g + 8) * 128;
#pragma unroll
    for (int nt = 0; nt < 16; ++nt) {
        int c0 = nt * 8 + 2 * t;
        uint32_t h, l;
        split2(O[nt][0] * inv0, O[nt][1] * inv0, h, l);
        *reinterpret_cast<uint32_t*>(g_xrh + out0 + c0) = h;
        *reinterpret_cast<uint32_t*>(g_xrl + out0 + c0) = l;
        split2(O[nt][2] * inv1, O[nt][3] * inv1, h, l);
        *reinterpret_cast<uint32_t*>(g_xrh + out1 + c0) = h;
        *reinterpret_cast<uint32_t*>(g_xrl + out1 + c0) = l;
    }
}

// ======================================================================
// BN finalize + epilogue
// ======================================================================
__global__ void k_stats()
{
    int f = threadIdx.x;
    float s = 0.f, q = 0.f;
    for (int b = 0; b < NQ / 64; ++b) {
        s += g_psum[b * 128 + f];
        q += g_psq [b * 128 + f];
    }
    float mean = s * (1.f / NQ);
    float var  = q * (1.f / NQ) - mean * mean;
    g_mean[f] = mean;
    g_rstd[f] = rsqrtf(var + BN_EPS);
}

__global__ void k_final(const float* __restrict__ gamma, const float* __restrict__ beta,
                        float* __restrict__ out)
{
    int idx = blockIdx.x * 256 + threadIdx.x;
    int f   = (idx & 31) * 4;
    float4 tv = *reinterpret_cast<const float4*>(g_t    + (size_t)idx * 4);
    float4 xd = *reinterpret_cast<const float4*>(g_xdec + (size_t)idx * 4);
    float4 r;
    r.x = xd.x + (tv.x - g_mean[f + 0]) * g_rstd[f + 0] * gamma[f + 0] + beta[f + 0];
    r.y = xd.y + (tv.y - g_mean[f + 1]) * g_rstd[f + 1] * gamma[f + 1] + beta[f + 1];
    r.z = xd.z + (tv.z - g_mean[f + 2]) * g_rstd[f + 2] * gamma[f + 2] + beta[f + 2];
    r.w = xd.w + (tv.w - g_mean[f + 3]) * g_rstd[f + 3] * gamma[f + 3] + beta[f + 3];
    *reinterpret_cast<float4*>(out + (size_t)idx * 4) = r;
}

// ======================================================================
extern "C" void kernel_launch(void* const* d_in, const int* in_sizes, int n_in,
                              void* d_out, int out_size)
{
    const float* xdec_f = (const float*)d_in[0];
    const float* xenc_f = (const float*)d_in[1];
    const int*   nbr    = (const int*)  d_in[2];
    const float* Wp1    = (const float*)d_in[3];
    const float* Wq     = (const float*)d_in[4];
    const float* Wk     = (const float*)d_in[5];
    const float* Wv     = (const float*)d_in[6];
    const float* Wt     = (const float*)d_in[7];
    const float* gamma  = (const float*)d_in[8];
    const float* beta   = (const float*)d_in[9];
    float* out = (float*)d_out;

    __nv_bfloat16 *p_xdh, *p_xdl, *p_xrh, *p_xrl;
    __nv_bfloat16 *p_wqh, *p_wql, *p_wth, *p_wtl;
    __nv_bfloat16 *p_qh, *p_ql;
    float *p_t;
    cudaGetSymbolAddress((void**)&p_xdh, g_xdh);  cudaGetSymbolAddress((void**)&p_xdl, g_xdl);
    cudaGetSymbolAddress((void**)&p_xrh, g_xrh);  cudaGetSymbolAddress((void**)&p_xrl, g_xrl);
    cudaGetSymbolAddress((void**)&p_wqh, g_wqh);  cudaGetSymbolAddress((void**)&p_wql, g_wql);
    cudaGetSymbolAddress((void**)&p_wth, g_wth);  cudaGetSymbolAddress((void**)&p_wtl, g_wtl);
    cudaGetSymbolAddress((void**)&p_qh,  g_qh);   cudaGetSymbolAddress((void**)&p_ql,  g_ql);
    cudaGetSymbolAddress((void**)&p_t,   g_t);

    cudaFuncSetAttribute(k_p1_mma,  cudaFuncAttributeMaxDynamicSharedMemorySize, 2 * GSTG);
    cudaFuncSetAttribute(k_projKV,  cudaFuncAttributeMaxDynamicSharedMemorySize, KVSMSZ);
    cudaFuncSetAttribute(k_proj<128, true,  false>, cudaFuncAttributeMaxDynamicSharedMemorySize, GSMSZ);
    cudaFuncSetAttribute(k_proj<128, false, true >, cudaFuncAttributeMaxDynamicSharedMemorySize, GSMSZ);
    cudaFuncSetAttribute(k_attn,    cudaFuncAttributeMaxDynamicSharedMemorySize, ASMSZ2);

    k_split7<<<SB6 / 1024, 256>>>(xdec_f, xenc_f, Wp1, Wk, Wv, Wq, Wt);
    k_p1_mma<<<NQ / 64, 256, 2 * GSTG>>>(nbr);
    k_projKV<<<NKV / 64, 256, KVSMSZ>>>();
    k_proj<128, true,  false><<<NQ / 64, 256, GSMSZ>>>(p_xdh, p_xdl, p_wqh, p_wql, p_qh, p_ql, nullptr);
    k_attn<<<dim3(NQB / 128, NBATCH), 256, ASMSZ2>>>();
    k_proj<128, false, true ><<<NQ / 64, 256, GSMSZ>>>(p_xrh, p_xrl, p_wth, p_wtl, nullptr, nullptr, p_t);
    k_stats<<<1, 128>>>();
    k_final<<<(NQ * NF / 4) / 256, 256>>>(gamma, beta, out);
}

// round 13
// speedup vs baseline: 2.0253x; 2.0253x over previous
#include <cuda_runtime.h>
#include <cuda_bf16.h>
#include <cuda_fp16.h>
#include <cstdint>

#define NQ      16384
#define NKV     32768
#define DEC     64
#define NF      128
#define NBATCH  8
#define NQB     2048
#define NKB     4096
#define BN_EPS  1e-4f

// ---------------- scratch (alloc-free: device globals) ----------------
__device__ float g_xdec[NQ * NF];
__device__ float g_t   [NQ * NF];
__device__ float g_psum[(NQ / 64) * NF];
__device__ float g_psq [(NQ / 64) * NF];
__device__ float g_mean[NF];
__device__ float g_rstd[NF];
__device__ __nv_bfloat16 g_dfh[NQ * DEC],  g_dfl[NQ * DEC];
__device__ __nv_bfloat16 g_eh [NKV * DEC], g_el [NKV * DEC];
__device__ __nv_bfloat16 g_wp1h[27 * 64 * 128], g_wp1l[27 * 64 * 128];
__device__ __nv_bfloat16 g_wkh[64 * 128],  g_wkl[64 * 128];
__device__ __nv_bfloat16 g_wvh[64 * 128],  g_wvl[64 * 128];
__device__ __nv_bfloat16 g_wqh[128 * 128], g_wql[128 * 128];
__device__ __nv_bfloat16 g_wth[128 * 128], g_wtl[128 * 128];
__device__ __nv_bfloat16 g_xdh[NQ * NF],  g_xdl[NQ * NF];
__device__ __nv_bfloat16 g_qh[NQ * NF],   g_ql[NQ * NF];
__device__ __nv_bfloat16 g_kh[NKV * NF],  g_kl[NKV * NF];
__device__ __half        g_vh[NKV * NF];                     // plain fp16 V
__device__ __nv_bfloat16 g_xrh[NQ * NF],  g_xrl[NQ * NF];

// ---------------- helpers ----------------
__device__ __forceinline__ uint32_t packb(__nv_bfloat16 x, __nv_bfloat16 y) {
    __nv_bfloat162 v(x, y);
    return *reinterpret_cast<uint32_t*>(&v);
}
__device__ __forceinline__ void split2(float a, float b, uint32_t& hi, uint32_t& lo) {
    __nv_bfloat16 ah = __float2bfloat16(a);
    __nv_bfloat16 bh = __float2bfloat16(b);
    float ar = a - __bfloat162float(ah);
    float br = b - __bfloat162float(bh);
    hi = packb(ah, bh);
    lo = packb(__float2bfloat16(ar), __float2bfloat16(br));
}
__device__ __forceinline__ uint32_t packh(float a, float b) {
    __half2 h = __floats2half2_rn(a, b);
    return *reinterpret_cast<uint32_t*>(&h);
}
__device__ __forceinline__ void mma16816(float* d, const uint32_t* a, const uint32_t* b) {
    asm volatile("mma.sync.aligned.m16n8k16.row.col.f32.bf16.bf16.f32 "
                 "{%0,%1,%2,%3}, {%4,%5,%6,%7}, {%8,%9}, {%0,%1,%2,%3};"
                 : "+f"(d[0]), "+f"(d[1]), "+f"(d[2]), "+f"(d[3])
                 : "r"(a[0]), "r"(a[1]), "r"(a[2]), "r"(a[3]), "r"(b[0]), "r"(b[1]));
}
__device__ __forceinline__ void mma16816h(float* d, const uint32_t* a, const uint32_t* b) {
    asm volatile("mma.sync.aligned.m16n8k16.row.col.f32.f16.f16.f32 "
                 "{%0,%1,%2,%3}, {%4,%5,%6,%7}, {%8,%9}, {%0,%1,%2,%3};"
                 : "+f"(d[0]), "+f"(d[1]), "+f"(d[2]), "+f"(d[3])
                 : "r"(a[0]), "r"(a[1]), "r"(a[2]), "r"(a[3]), "r"(b[0]), "r"(b[1]));
}
__device__ __forceinline__ void ldsm4(uint32_t* r, uint32_t addr) {
    asm volatile("ldmatrix.sync.aligned.m8n8.x4.shared.b16 {%0,%1,%2,%3}, [%4];"
                 : "=r"(r[0]), "=r"(r[1]), "=r"(r[2]), "=r"(r[3]) : "r"(addr));
}
__device__ __forceinline__ void ldsm4t(uint32_t* r, uint32_t addr) {
    asm volatile("ldmatrix.sync.aligned.m8n8.x4.trans.shared.b16 {%0,%1,%2,%3}, [%4];"
                 : "=r"(r[0]), "=r"(r[1]), "=r"(r[2]), "=r"(r[3]) : "r"(addr));
}
__device__ __forceinline__ void cpa16(uint32_t dst, const void* src) {
    asm volatile("cp.async.cg.shared.global [%0], [%1], 16;" :: "r"(dst), "l"(src));
}
__device__ __forceinline__ void cpa_commit() {
    asm volatile("cp.async.commit_group;");
}

// ======================================================================
// Split-prep
// ======================================================================
#define SB0 (NQ * DEC)
#define SB1 (SB0 + NKV * DEC)
#define SB2 (SB1 + 27 * 64 * 128)
#define SB3 (SB2 + 64 * 128)
#define SB4 (SB3 + 64 * 128)
#define SB5 (SB4 + 128 * 128)
#define SB6 (SB5 + 128 * 128)

__device__ __forceinline__ void split4(float4 v, uint2& h, uint2& l) {
    uint32_t h0, l0, h1, l1;
    split2(v.x, v.y, h0, l0);
    split2(v.z, v.w, h1, l1);
    h = {h0, h1};
    l = {l0, l1};
}

__global__ void k_split7(const float* __restrict__ xdf, const float* __restrict__ xef,
                         const float* __restrict__ Wp1, const float* __restrict__ Wk,
                         const float* __restrict__ Wv,  const float* __restrict__ Wq,
                         const float* __restrict__ Wt)
{
    int e = (blockIdx.x * 256 + threadIdx.x) * 4;
    const float* src; __nv_bfloat16 *dh, *dl; int off;
    if      (e < SB0) { src = xdf; dh = g_dfh;  dl = g_dfl;  off = e; }
    else if (e < SB1) { src = xef; dh = g_eh;   dl = g_el;   off = e - SB0; }
    else if (e < SB2) { src = Wp1; dh = g_wp1h; dl = g_wp1l; off = e - SB1; }
    else if (e < SB3) { src = Wk;  dh = g_wkh;  dl = g_wkl;  off = e - SB2; }
    else if (e < SB4) { src = Wv;  dh = g_wvh;  dl = g_wvl;  off = e - SB3; }
    else if (e < SB5) { src = Wq;  dh = g_wqh;  dl = g_wql;  off = e - SB4; }
    else              { src = Wt;  dh = g_wth;  dl = g_wtl;  off = e - SB5; }
    float4 v = *reinterpret_cast<const float4*>(src + off);
    uint2 h, l;
    split4(v, h, l);
    *reinterpret_cast<uint2*>(dh + off) = h;
    *reinterpret_cast<uint2*>(dl + off) = l;
}

// ======================================================================
// Shared HMMA tile machinery (64x128 tile, 8 warps as 4 qw x 2 nw)
// ======================================================================
#define GOAH  0
#define GOAL  9216
#define GOBH  18432
#define GOBL  35840
#define GSTG  53248
#define GSMSZ (GSTG + 4096)

__device__ __forceinline__ void mma_tile64(uint32_t sbase,
                                           uint32_t bOffH, uint32_t bOffL,
                                           int qw, int nw, int lane,
                                           float acc[8][4])
{
    const int rA = lane & 15, cA = (lane >> 4) * 8;
    const int rV = ((lane >> 3) & 1) * 8 + (lane & 7);
    const int cV = ((lane >> 3) & 2) * 4;
#pragma unroll
    for (int kc = 0; kc < 4; ++kc) {
        uint32_t Aaddr = sbase + (uint32_t)((qw * 16 + rA) * 72 + kc * 16 + cA) * 2;
        uint32_t Ah4[4], Al4[4];
        ldsm4(Ah4, Aaddr + GOAH);
        ldsm4(Al4, Aaddr + GOAL);
#pragma unroll
        for (int nt2 = 0; nt2 < 4; ++nt2) {
            uint32_t ra = (uint32_t)((kc * 16 + rV) * 136 + nw * 64 + nt2 * 16 + cV) * 2;
            uint32_t Bh4[4], Bl4[4];
            ldsm4t(Bh4, sbase + bOffH + ra);
            ldsm4t(Bl4, sbase + bOffL + ra);
            float* a0 = acc[nt2 * 2];
            float* a1 = acc[nt2 * 2 + 1];
            mma16816(a0, Ah4, Bh4);  mma16816(a1, Ah4, Bh4 + 2);
            mma16816(a0, Ah4, Bl4);  mma16816(a1, Ah4, Bl4 + 2);
            mma16816(a0, Al4, Bh4);  mma16816(a1, Al4, Bh4 + 2);
        }
    }
}

// ======================================================================
// p1 gather-conv (unchanged winner)
// ======================================================================
__global__ __launch_bounds__(256) void k_p1_mma(const int* __restrict__ nbr)
{
    extern __shared__ char smr[];
    const uint32_t sbase = (uint32_t)__cvta_generic_to_shared(smr);
    const int tid = threadIdx.x;
    const int wid = tid >> 5, lane = tid & 31;
    const int qw = wid >> 1, nw = wid & 1;
    const int m0 = blockIdx.x * 64;

    float acc[8][4];
#pragma unroll
    for (int i = 0; i < 8; ++i)
#pragma unroll
        for (int j = 0; j < 4; ++j) acc[i][j] = 0.f;

    auto prefetch = [&](int k, int s) {
        uint32_t sb = sbase + s * GSTG;
#pragma unroll
        for (int i = 0; i < 2; ++i) {
            int idx = tid + i * 256;
            int r = idx >> 3, c = idx & 7;
            int gi = nbr[(m0 + r) * 27 + k];
            uint32_t so = (uint32_t)(r * 72 + c * 8) * 2;
            cpa16(sb + GOAH + so, g_dfh + (size_t)gi * DEC + c * 8);
            cpa16(sb + GOAL + so, g_dfl + (size_t)gi * DEC + c * 8);
        }
        const __nv_bfloat16* wh = g_wp1h + (size_t)k * 64 * 128;
        const __nv_bfloat16* wl = g_wp1l + (size_t)k * 64 * 128;
#pragma unroll
        for (int i = 0; i < 4; ++i) {
            int idx = tid + i * 256;
            int r = idx >> 4, c = idx & 15;
            uint32_t so = (uint32_t)(r * 136 + c * 8) * 2;
            cpa16(sb + GOBH + so, wh + r * 128 + c * 8);
            cpa16(sb + GOBL + so, wl + r * 128 + c * 8);
        }
        cpa_commit();
    };

    prefetch(0, 0);
    for (int k = 0; k < 27; ++k) {
        const int s = k & 1;
        if (k + 1 < 27) {
            prefetch(k + 1, s ^ 1);
            asm volatile("cp.async.wait_group 1;");
        } else {
            asm volatile("cp.async.wait_group 0;");
        }
        __syncthreads();
        mma_tile64(sbase + s * GSTG, GOBH, GOBL, qw, nw, lane, acc);
        __syncthreads();
    }

    const int g = lane >> 2, t = lane & 3;
    const int r0 = m0 + qw * 16 + g, r1 = r0 + 8;
#pragma unroll
    for (int nt = 0; nt < 8; ++nt) {
        int col = nw * 64 + nt * 8 + 2 * t;
        float2 v0 = {acc[nt][0], acc[nt][1]};
        float2 v1 = {acc[nt][2], acc[nt][3]};
        *reinterpret_cast<float2*>(g_xdec + (size_t)r0 * 128 + col) = v0;
        *reinterpret_cast<float2*>(g_xdec + (size_t)r1 * 128 + col) = v1;
        uint32_t h, l;
        split2(v0.x, v0.y, h, l);
        *reinterpret_cast<uint32_t*>(g_xdh + (size_t)r0 * 128 + col) = h;
        *reinterpret_cast<uint32_t*>(g_xdl + (size_t)r0 * 128 + col) = l;
        split2(v1.x, v1.y, h, l);
        *reinterpret_cast<uint32_t*>(g_xdh + (size_t)r1 * 128 + col) = h;
        *reinterpret_cast<uint32_t*>(g_xdl + (size_t)r1 * 128 + col) = l;
    }
}

// ======================================================================
// Fused K+V projection: K split-bf16, V plain fp16
// ======================================================================
#define KV_BKH 18432
#define KV_BKL (KV_BKH + 17408)
#define KV_BVH (KV_BKH + 34816)
#define KV_BVL (KV_BVH + 17408)
#define KVSMSZ (KV_BVH + 34816)

__global__ __launch_bounds__(256) void k_projKV()
{
    extern __shared__ char smr[];
    const uint32_t sbase = (uint32_t)__cvta_generic_to_shared(smr);
    const int tid = threadIdx.x;
    const int wid = tid >> 5, lane = tid & 31;
    const int qw = wid >> 1, nw = wid & 1;
    const int m0 = blockIdx.x * 64;

#pragma unroll
    for (int i = 0; i < 2; ++i) {
        int idx = tid + i * 256;
        int r = idx >> 3, c = idx & 7;
        size_t go = (size_t)(m0 + r) * DEC + c * 8;
        uint32_t so = (uint32_t)(r * 72 + c * 8) * 2;
        cpa16(sbase + GOAH + so, g_eh + go);
        cpa16(sbase + GOAL + so, g_el + go);
    }
#pragma unroll
    for (int i = 0; i < 4; ++i) {
        int idx = tid + i * 256;
        int r = idx >> 4, c = idx & 15;
        size_t go = (size_t)r * 128 + c * 8;
        uint32_t so = (uint32_t)(r * 136 + c * 8) * 2;
        cpa16(sbase + KV_BKH + so, g_wkh + go);
        cpa16(sbase + KV_BKL + so, g_wkl + go);
        cpa16(sbase + KV_BVH + so, g_wvh + go);
        cpa16(sbase + KV_BVL + so, g_wvl + go);
    }
    cpa_commit();
    asm volatile("cp.async.wait_group 0;");
    __syncthreads();

    float accK[8][4], accV[8][4];
#pragma unroll
    for (int i = 0; i < 8; ++i)
#pragma unroll
        for (int j = 0; j < 4; ++j) { accK[i][j] = 0.f; accV[i][j] = 0.f; }

    mma_tile64(sbase, KV_BKH, KV_BKL, qw, nw, lane, accK);
    mma_tile64(sbase, KV_BVH, KV_BVL, qw, nw, lane, accV);

    const int g = lane >> 2, t = lane & 3;
    const int r0 = m0 + qw * 16 + g, r1 = r0 + 8;
#pragma unroll
    for (int nt = 0; nt < 8; ++nt) {
        int col = nw * 64 + nt * 8 + 2 * t;
        uint32_t h, l;
        split2(accK[nt][0], accK[nt][1], h, l);
        *reinterpret_cast<uint32_t*>(g_kh + (size_t)r0 * 128 + col) = h;
        *reinterpret_cast<uint32_t*>(g_kl + (size_t)r0 * 128 + col) = l;
        split2(accK[nt][2], accK[nt][3], h, l);
        *reinterpret_cast<uint32_t*>(g_kh + (size_t)r1 * 128 + col) = h;
        *reinterpret_cast<uint32_t*>(g_kl + (size_t)r1 * 128 + col) = l;
        *reinterpret_cast<uint32_t*>(g_vh + (size_t)r0 * 128 + col) =
            packh(accV[nt][0], accV[nt][1]);
        *reinterpret_cast<uint32_t*>(g_vh + (size_t)r1 * 128 + col) =
            packh(accV[nt][2], accV[nt][3]);
    }
}

// ======================================================================
// Generic split-bf16 HMMA GEMM (+ split out / BN stats) — unchanged winner
// ======================================================================
template <int KA, bool SPLIT, bool STATS>
__global__ __launch_bounds__(256) void k_proj(const __nv_bfloat16* __restrict__ Ahg,
                                              const __nv_bfloat16* __restrict__ Alg,
                                              const __nv_bfloat16* __restrict__ Bhg,
                                              const __nv_bfloat16* __restrict__ Blg,
                                              __nv_bfloat16* __restrict__ Ch,
                                              __nv_bfloat16* __restrict__ Cl,
                                              float* __restrict__ Cf)
{
    extern __shared__ char smr[];
    const uint32_t sbase = (uint32_t)__cvta_generic_to_shared(smr);
    const int tid = threadIdx.x;
    const int wid = tid >> 5, lane = tid & 31;
    const int qw = wid >> 1, nw = wid & 1;
    const int m0 = blockIdx.x * 64;

    float acc[8][4];
#pragma unroll
    for (int i = 0; i < 8; ++i)
#pragma unroll
        for (int j = 0; j < 4; ++j) acc[i][j] = 0.f;

#pragma unroll
    for (int kb = 0; kb < KA / 64; ++kb) {
        __syncthreads();
#pragma unroll
        for (int i = 0; i < 2; ++i) {
            int idx = tid + i * 256;
            int r = idx >> 3, c = idx & 7;
            size_t go = (size_t)(m0 + r) * KA + kb * 64 + c * 8;
            uint32_t so = (uint32_t)(r * 72 + c * 8) * 2;
            cpa16(sbase + GOAH + so, Ahg + go);
            cpa16(sbase + GOAL + so, Alg + go);
        }
#pragma unroll
        for (int i = 0; i < 4; ++i) {
            int idx = tid + i * 256;
            int r = idx >> 4, c = idx & 15;
            size_t go = (size_t)(kb * 64 + r) * 128 + c * 8;
            uint32_t so = (uint32_t)(r * 136 + c * 8) * 2;
            cpa16(sbase + GOBH + so, Bhg + go);
            cpa16(sbase + GOBL + so, Blg + go);
        }
        cpa_commit();
        asm volatile("cp.async.wait_group 0;");
        __syncthreads();
        mma_tile64(sbase, GOBH, GOBL, qw, nw, lane, acc);
    }

    const int g = lane >> 2, t = lane & 3;
    const int r0 = m0 + qw * 16 + g, r1 = r0 + 8;
#pragma unroll
    for (int nt = 0; nt < 8; ++nt) {
        int col = nw * 64 + nt * 8 + 2 * t;
        if (SPLIT) {
            uint32_t h, l;
            split2(acc[nt][0], acc[nt][1], h, l);
            *reinterpret_cast<uint32_t*>(Ch + (size_t)r0 * 128 + col) = h;
            *reinterpret_cast<uint32_t*>(Cl + (size_t)r0 * 128 + col) = l;
            split2(acc[nt][2], acc[nt][3], h, l);
            *reinterpret_cast<uint32_t*>(Ch + (size_t)r1 * 128 + col) = h;
            *reinterpret_cast<uint32_t*>(Cl + (size_t)r1 * 128 + col) = l;
        } else {
            float2 v0 = {acc[nt][0], acc[nt][1]};
            float2 v1 = {acc[nt][2], acc[nt][3]};
            *reinterpret_cast<float2*>(Cf + (size_t)r0 * 128 + col) = v0;
            *reinterpret_cast<float2*>(Cf + (size_t)r1 * 128 + col) = v1;
        }
    }

    if (STATS) {
        float* sS = reinterpret_cast<float*>(smr);
        float* sQ = reinterpret_cast<float*>(smr + 2048);
        __syncthreads();
        float cs[8][2], cq[8][2];
#pragma unroll
        for (int nt = 0; nt < 8; ++nt) {
            cs[nt][0] = acc[nt][0] + acc[nt][2];
            cs[nt][1] = acc[nt][1] + acc[nt][3];
            cq[nt][0] = acc[nt][0] * acc[nt][0] + acc[nt][2] * acc[nt][2];
            cq[nt][1] = acc[nt][1] * acc[nt][1] + acc[nt][3] * acc[nt][3];
        }
#pragma unroll
        for (int off = 4; off < 32; off <<= 1) {
#pragma unroll
            for (int nt = 0; nt < 8; ++nt) {
                cs[nt][0] += __shfl_xor_sync(0xffffffffu, cs[nt][0], off);
                cs[nt][1] += __shfl_xor_sync(0xffffffffu, cs[nt][1], off);
                cq[nt][0] += __shfl_xor_sync(0xffffffffu, cq[nt][0], off);
                cq[nt][1] += __shfl_xor_sync(0xffffffffu, cq[nt][1], off);
            }
        }
        if (lane < 4) {
#pragma unroll
            for (int nt = 0; nt < 8; ++nt) {
                int col = nw * 64 + nt * 8 + 2 * lane;
                sS[qw * 128 + col]     = cs[nt][0];
                sS[qw * 128 + col + 1] = cs[nt][1];
                sQ[qw * 128 + col]     = cq[nt][0];
                sQ[qw * 128 + col + 1] = cq[nt][1];
            }
        }
        __syncthreads();
        if (tid < 128) {
            float s = sS[tid] + sS[128 + tid] + sS[256 + tid] + sS[384 + tid];
            float q = sQ[tid] + sQ[128 + tid] + sQ[256 + tid] + sQ[384 + tid];
            g_psum[blockIdx.x * 128 + tid] = s;
            g_psq [blockIdx.x * 128 + tid] = q;
        }
    }
}

// ======================================================================
// Flash attention (round-9 structure, V single-fp16 PV):
// 128 q-rows/block, 256 threads, kv-tile 64 as two interleaved 32-halves,
// warp-private softmax, Q in regs, cp.async double-buffered.
// stage = KH | KL | VH (3 x 17408 B)
// ======================================================================
#define STG   17408
#define SSTAGE (3 * STG)              // 52224
#define ASMSZ2 (2 * SSTAGE)           // 104448

__global__ __launch_bounds__(256, 1) void k_attn()
{
    extern __shared__ char smr[];
    const uint32_t sbase = (uint32_t)__cvta_generic_to_shared(smr);

    const int tid  = threadIdx.x;
    const int w    = tid >> 5, lane = tid & 31;
    const int g    = lane >> 2, t = lane & 3;
    const int b    = blockIdx.y;
    const size_t qrow0 = (size_t)b * NQB + blockIdx.x * 128;

    const int rA = lane & 15;
    const int cA = (lane >> 4) * 8;
    const int rB = ((lane >> 3) & 2) * 4 + (lane & 7);
    const int cB = ((lane >> 3) & 1) * 8;
    const int rV = ((lane >> 3) & 1) * 8 + (lane & 7);
    const int cV = ((lane >> 3) & 2) * 4;

    // ---- stage Q, load register A-fragments ----
    uint32_t Qh[8][4], Ql[8][4];
    {
        const __nv_bfloat16* qh = g_qh + qrow0 * 128;
        const __nv_bfloat16* ql = g_ql + qrow0 * 128;
#pragma unroll
        for (int i = 0; i < 8; ++i) {
            int idx = tid + i * 256;
            int r = idx >> 4, c = idx & 15;
            uint32_t so = (uint32_t)(r * 136 + c * 8) * 2;
            cpa16(sbase + so,         qh + (size_t)r * 128 + c * 8);
            cpa16(sbase + 34816 + so, ql + (size_t)r * 128 + c * 8);
        }
        cpa_commit();
        asm volatile("cp.async.wait_group 0;");
        __syncthreads();
#pragma unroll
        for (int ch = 0; ch < 8; ++ch) {
            uint32_t Aaddr = sbase + (uint32_t)((w * 16 + rA) * 136 + ch * 16 + cA) * 2;
            ldsm4(Qh[ch], Aaddr);
            ldsm4(Ql[ch], Aaddr + 34816);
        }
        __syncthreads();
    }

    float O[16][4];
#pragma unroll
    for (int i = 0; i < 16; ++i)
#pragma unroll
        for (int j = 0; j < 4; ++j) O[i][j] = 0.f;
    float m0r = -1e30f, m1r = -1e30f, l0 = 0.f, l1 = 0.f;

    const size_t kvbase = (size_t)b * NKB * 128;
    auto prefetch = [&](int jt, int s) {
        size_t base = kvbase + (size_t)jt * 64 * 128;
        uint32_t sb = sbase + s * SSTAGE;
#pragma unroll
        for (int i = 0; i < 12; ++i) {
            int arr = i >> 2;                    // 0:KH 1:KL 2:VH
            int idx = tid + (i & 3) * 256;
            int r = idx >> 4, c = idx & 15;
            uint32_t so = sb + arr * STG + (uint32_t)(r * 136 + c * 8) * 2;
            size_t eo = base + (size_t)r * 128 + c * 8;
            const void* src;
            if      (arr == 0) src = g_kh + eo;
            else if (arr == 1) src = g_kl + eo;
            else               src = g_vh + eo;
            cpa16(so, src);
        }
        cpa_commit();
    };

    prefetch(0, 0);

    const int NIT = NKB / 64;
    for (int jt = 0; jt < NIT; ++jt) {
        const int s = jt & 1;
        if (jt + 1 < NIT) {
            prefetch(jt + 1, s ^ 1);
            asm volatile("cp.async.wait_group 1;");
        } else {
            asm volatile("cp.async.wait_group 0;");
        }
        __syncthreads();

        const uint32_t KHb = sbase + s * SSTAGE;
        const uint32_t KLb = KHb + STG;
        const uint32_t VHb = KHb + 2 * STG;

        // ---- S for BOTH halves (back-to-back MMA issue) ----
        float sA[8][4];
#pragma unroll
        for (int i = 0; i < 8; ++i)
#pragma unroll
            for (int j = 0; j < 4; ++j) sA[i][j] = 0.f;

#pragma unroll
        for (int half = 0; half < 2; ++half) {
#pragma unroll
            for (int ch = 0; ch < 8; ++ch) {
                uint32_t col = (uint32_t)(ch * 16 + cB) * 2;
#pragma unroll
                for (int r4h = 0; r4h < 2; ++r4h) {
                    int r4 = half * 2 + r4h;
                    uint32_t ra = (uint32_t)((r4 * 16 + rB) * 136) * 2 + col;
                    uint32_t bh[4], bl[4];
                    ldsm4(bh, KHb + ra);
                    ldsm4(bl, KLb + ra);
                    float* s0 = sA[r4 * 2];
                    float* s1 = sA[r4 * 2 + 1];
                    mma16816(s0, Qh[ch], bh);      mma16816(s1, Qh[ch], bh + 2);
                    mma16816(s0, Qh[ch], bl);      mma16816(s1, Qh[ch], bl + 2);
                    mma16816(s0, Ql[ch], bh);      mma16816(s1, Ql[ch], bh + 2);
                }
            }
        }

        // ---- per-half softmax + PV (straight-line) ----
#pragma unroll
        for (int half = 0; half < 2; ++half) {
            float (*sH)[4] = &sA[half * 4];

            float rm0 = sH[0][0], rm1 = sH[0][2];
#pragma unroll
            for (int nt = 0; nt < 4; ++nt) {
                rm0 = fmaxf(rm0, fmaxf(sH[nt][0], sH[nt][1]));
                rm1 = fmaxf(rm1, fmaxf(sH[nt][2], sH[nt][3]));
            }
            rm0 = fmaxf(rm0, __shfl_xor_sync(0xffffffffu, rm0, 1));
            rm0 = fmaxf(rm0, __shfl_xor_sync(0xffffffffu, rm0, 2));
            rm1 = fmaxf(rm1, __shfl_xor_sync(0xffffffffu, rm1, 1));
            rm1 = fmaxf(rm1, __shfl_xor_sync(0xffffffffu, rm1, 2));
            float mn0 = fmaxf(m0r, rm0);
            float mn1 = fmaxf(m1r, rm1);
            float sc0 = __expf(m0r - mn0);
            float sc1 = __expf(m1r - mn1);

            float p[4][4];
            float ls0 = 0.f, ls1 = 0.f;
#pragma unroll
            for (int nt = 0; nt < 4; ++nt) {
                p[nt][0] = __expf(sH[nt][0] - mn0);
                p[nt][1] = __expf(sH[nt][1] - mn0);
                p[nt][2] = __expf(sH[nt][2] - mn1);
                p[nt][3] = __expf(sH[nt][3] - mn1);
                ls0 += p[nt][0] + p[nt][1];
                ls1 += p[nt][2] + p[nt][3];
            }
            ls0 += __shfl_xor_sync(0xffffffffu, ls0, 1);
            ls0 += __shfl_xor_sync(0xffffffffu, ls0, 2);
            ls1 += __shfl_xor_sync(0xffffffffu, ls1, 1);
            ls1 += __shfl_xor_sync(0xffffffffu, ls1, 2);
            l0 = l0 * sc0 + ls0;
            l1 = l1 * sc1 + ls1;
            m0r = mn0; m1r = mn1;

#pragma unroll
            for (int nt = 0; nt < 16; ++nt) {
                O[nt][0] *= sc0; O[nt][1] *= sc0;
                O[nt][2] *= sc1; O[nt][3] *= sc1;
            }

            // P as plain fp16 A-fragments (2 k-chunks of 16 per half)
            uint32_t Ph[2][4];
#pragma unroll
            for (int c = 0; c < 2; ++c) {
                Ph[c][0] = packh(p[2 * c][0],     p[2 * c][1]);
                Ph[c][1] = packh(p[2 * c][2],     p[2 * c][3]);
                Ph[c][2] = packh(p[2 * c + 1][0], p[2 * c + 1][1]);
                Ph[c][3] = packh(p[2 * c + 1][2], p[2 * c + 1][3]);
            }

            // O += P(fp16) * V(fp16)
#pragma unroll
            for (int kcl = 0; kcl < 2; ++kcl) {
                int kc = half * 2 + kcl;
#pragma unroll
                for (int dp = 0; dp < 8; ++dp) {
                    uint32_t ra = (uint32_t)((kc * 16 + rV) * 136 + dp * 16 + cV) * 2;
                    uint32_t vh[4];
                    ldsm4t(vh, VHb + ra);
                    float* o0 = O[dp * 2];
                    float* o1 = O[dp * 2 + 1];
                    mma16816h(o0, Ph[kcl], vh);    mma16816h(o1, Ph[kcl], vh + 2);
                }
            }
        }
        __syncthreads();
    }

    // ---- epilogue: normalize, split, store ----
    float inv0 = 1.f / l0, inv1 = 1.f / l1;
    size_t out0 = (qrow0 + w * 16 + g) * 128;
    size_t out1 = (qrow0 + w * 16 + g + 8) * 128;
#pragma unroll
    for (int nt = 0; nt < 16; ++nt) {
        int c0 = nt * 8 + 2 * t;
        uint32_t h, l;
        split2(O[nt][0] * inv0, O[nt][1] * inv0, h, l);
        *reinterpret_cast<uint32_t*>(g_xrh + out0 + c0) = h;
        *reinterpret_cast<uint32_t*>(g_xrl + out0 + c0) = l;
        split2(O[nt][2] * inv1, O[nt][3] * inv1, h, l);
        *reinterpret_cast<uint32_t*>(g_xrh + out1 + c0) = h;
        *reinterpret_cast<uint32_t*>(g_xrl + out1 + c0) = l;
    }
}

// ======================================================================
// BN finalize + epilogue
// ======================================================================
__global__ void k_stats()
{
    int f = threadIdx.x;
    float s = 0.f, q = 0.f;
    for (int b = 0; b < NQ / 64; ++b) {
        s += g_psum[b * 128 + f];
        q += g_psq [b * 128 + f];
    }
    float mean = s * (1.f / NQ);
    float var  = q * (1.f / NQ) - mean * mean;
    g_mean[f] = mean;
    g_rstd[f] = rsqrtf(var + BN_EPS);
}

__global__ void k_final(const float* __restrict__ gamma, const float* __restrict__ beta,
                        float* __restrict__ out)
{
    int idx = blockIdx.x * 256 + threadIdx.x;
    int f   = (idx & 31) * 4;
    float4 tv = *reinterpret_cast<const float4*>(g_t    + (size_t)idx * 4);
    float4 xd = *reinterpret_cast<const float4*>(g_xdec + (size_t)idx * 4);
    float4 r;
    r.x = xd.x + (tv.x - g_mean[f + 0]) * g_rstd[f + 0] * gamma[f + 0] + beta[f + 0];
    r.y = xd.y + (tv.y - g_mean[f + 1]) * g_rstd[f + 1] * gamma[f + 1] + beta[f + 1];
    r.z = xd.z + (tv.z - g_mean[f + 2]) * g_rstd[f + 2] * gamma[f + 2] + beta[f + 2];
    r.w = xd.w + (tv.w - g_mean[f + 3]) * g_rstd[f + 3] * gamma[f + 3] + beta[f + 3];
    *reinterpret_cast<float4*>(out + (size_t)idx * 4) = r;
}

// ======================================================================
extern "C" void kernel_launch(void* const* d_in, const int* in_sizes, int n_in,
                              void* d_out, int out_size)
{
    const float* xdec_f = (const float*)d_in[0];
    const float* xenc_f = (const float*)d_in[1];
    const int*   nbr    = (const int*)  d_in[2];
    const float* Wp1    = (const float*)d_in[3];
    const float* Wq     = (const float*)d_in[4];
    const float* Wk     = (const float*)d_in[5];
    const float* Wv     = (const float*)d_in[6];
    const float* Wt     = (const float*)d_in[7];
    const float* gamma  = (const float*)d_in[8];
    const float* beta   = (const float*)d_in[9];
    float* out = (float*)d_out;

    __nv_bfloat16 *p_xdh, *p_xdl, *p_xrh, *p_xrl;
    __nv_bfloat16 *p_wqh, *p_wql, *p_wth, *p_wtl;
    __nv_bfloat16 *p_qh, *p_ql;
    float *p_t;
    cudaGetSymbolAddress((void**)&p_xdh, g_xdh);  cudaGetSymbolAddress((void**)&p_xdl, g_xdl);
    cudaGetSymbolAddress((void**)&p_xrh, g_xrh);  cudaGetSymbolAddress((void**)&p_xrl, g_xrl);
    cudaGetSymbolAddress((void**)&p_wqh, g_wqh);  cudaGetSymbolAddress((void**)&p_wql, g_wql);
    cudaGetSymbolAddress((void**)&p_wth, g_wth);  cudaGetSymbolAddress((void**)&p_wtl, g_wtl);
    cudaGetSymbolAddress((void**)&p_qh,  g_qh);   cudaGetSymbolAddress((void**)&p_ql,  g_ql);
    cudaGetSymbolAddress((void**)&p_t,   g_t);

    cudaFuncSetAttribute(k_p1_mma,  cudaFuncAttributeMaxDynamicSharedMemorySize, 2 * GSTG);
    cudaFuncSetAttribute(k_projKV,  cudaFuncAttributeMaxDynamicSharedMemorySize, KVSMSZ);
    cudaFuncSetAttribute(k_proj<128, true,  false>, cudaFuncAttributeMaxDynamicSharedMemorySize, GSMSZ);
    cudaFuncSetAttribute(k_proj<128, false, true >, cudaFuncAttributeMaxDynamicSharedMemorySize, GSMSZ);
    cudaFuncSetAttribute(k_attn,    cudaFuncAttributeMaxDynamicSharedMemorySize, ASMSZ2);

    k_split7<<<SB6 / 1024, 256>>>(xdec_f, xenc_f, Wp1, Wk, Wv, Wq, Wt);
    k_p1_mma<<<NQ / 64, 256, 2 * GSTG>>>(nbr);
    k_projKV<<<NKV / 64, 256, KVSMSZ>>>();
    k_proj<128, true,  false><<<NQ / 64, 256, GSMSZ>>>(p_xdh, p_xdl, p_wqh, p_wql, p_qh, p_ql, nullptr);
    k_attn<<<dim3(NQB / 128, NBATCH), 256, ASMSZ2>>>();
    k_proj<128, false, true ><<<NQ / 64, 256, GSMSZ>>>(p_xrh, p_xrl, p_wth, p_wtl, nullptr, nullptr, p_t);
    k_stats<<<1, 128>>>();
    k_final<<<(NQ * NF / 4) / 256, 256>>>(gamma, beta, out);
}

// round 14
// speedup vs baseline: 2.0498x; 1.0121x over previous
#include <cuda_runtime.h>
#include <cuda_bf16.h>
#include <cuda_fp16.h>
#include <cstdint>

#define NQ      16384
#define NKV     32768
#define DEC     64
#define NF      128
#define NBATCH  8
#define NQB     2048
#define NKB     4096
#define BN_EPS  1e-4f

// ---------------- scratch (alloc-free: device globals) ----------------
__device__ float g_xdec[NQ * NF];
__device__ float g_t   [NQ * NF];
__device__ float g_psum[(NQ / 64) * NF];
__device__ float g_psq [(NQ / 64) * NF];
__device__ float g_mean[NF];
__device__ float g_rstd[NF];
__device__ __nv_bfloat16 g_dfh[NQ * DEC],  g_dfl[NQ * DEC];
__device__ __nv_bfloat16 g_eh [NKV * DEC], g_el [NKV * DEC];
__device__ __nv_bfloat16 g_wp1h[27 * 64 * 128], g_wp1l[27 * 64 * 128];
__device__ __nv_bfloat16 g_wkh[64 * 128],  g_wkl[64 * 128];
__device__ __nv_bfloat16 g_wvh[64 * 128],  g_wvl[64 * 128];
__device__ __nv_bfloat16 g_wqh[128 * 128], g_wql[128 * 128];
__device__ __nv_bfloat16 g_wth[128 * 128], g_wtl[128 * 128];
__device__ __nv_bfloat16 g_xdh[NQ * NF],  g_xdl[NQ * NF];
__device__ __nv_bfloat16 g_qh[NQ * NF],   g_ql[NQ * NF];
__device__ __nv_bfloat16 g_kh[NKV * NF],  g_kl[NKV * NF];
__device__ __half        g_vh[NKV * NF];                     // plain fp16 V
__device__ __nv_bfloat16 g_xrh[NQ * NF],  g_xrl[NQ * NF];

// ---------------- helpers ----------------
__device__ __forceinline__ uint32_t packb(__nv_bfloat16 x, __nv_bfloat16 y) {
    __nv_bfloat162 v(x, y);
    return *reinterpret_cast<uint32_t*>(&v);
}
__device__ __forceinline__ void split2(float a, float b, uint32_t& hi, uint32_t& lo) {
    __nv_bfloat16 ah = __float2bfloat16(a);
    __nv_bfloat16 bh = __float2bfloat16(b);
    float ar = a - __bfloat162float(ah);
    float br = b - __bfloat162float(bh);
    hi = packb(ah, bh);
    lo = packb(__float2bfloat16(ar), __float2bfloat16(br));
}
__device__ __forceinline__ uint32_t packh(float a, float b) {
    __half2 h = __floats2half2_rn(a, b);
    return *reinterpret_cast<uint32_t*>(&h);
}
__device__ __forceinline__ void mma16816(float* d, const uint32_t* a, const uint32_t* b) {
    asm volatile("mma.sync.aligned.m16n8k16.row.col.f32.bf16.bf16.f32 "
                 "{%0,%1,%2,%3}, {%4,%5,%6,%7}, {%8,%9}, {%0,%1,%2,%3};"
                 : "+f"(d[0]), "+f"(d[1]), "+f"(d[2]), "+f"(d[3])
                 : "r"(a[0]), "r"(a[1]), "r"(a[2]), "r"(a[3]), "r"(b[0]), "r"(b[1]));
}
__device__ __forceinline__ void mma16816h(float* d, const uint32_t* a, const uint32_t* b) {
    asm volatile("mma.sync.aligned.m16n8k16.row.col.f32.f16.f16.f32 "
                 "{%0,%1,%2,%3}, {%4,%5,%6,%7}, {%8,%9}, {%0,%1,%2,%3};"
                 : "+f"(d[0]), "+f"(d[1]), "+f"(d[2]), "+f"(d[3])
                 : "r"(a[0]), "r"(a[1]), "r"(a[2]), "r"(a[3]), "r"(b[0]), "r"(b[1]));
}
__device__ __forceinline__ void ldsm4(uint32_t* r, uint32_t addr) {
    asm volatile("ldmatrix.sync.aligned.m8n8.x4.shared.b16 {%0,%1,%2,%3}, [%4];"
                 : "=r"(r[0]), "=r"(r[1]), "=r"(r[2]), "=r"(r[3]) : "r"(addr));
}
__device__ __forceinline__ void ldsm4t(uint32_t* r, uint32_t addr) {
    asm volatile("ldmatrix.sync.aligned.m8n8.x4.trans.shared.b16 {%0,%1,%2,%3}, [%4];"
                 : "=r"(r[0]), "=r"(r[1]), "=r"(r[2]), "=r"(r[3]) : "r"(addr));
}
__device__ __forceinline__ void cpa16(uint32_t dst, const void* src) {
    asm volatile("cp.async.cg.shared.global [%0], [%1], 16;" :: "r"(dst), "l"(src));
}
__device__ __forceinline__ void cpa_commit() {
    asm volatile("cp.async.commit_group;");
}

// ======================================================================
// Split-prep
// ======================================================================
#define SB0 (NQ * DEC)
#define SB1 (SB0 + NKV * DEC)
#define SB2 (SB1 + 27 * 64 * 128)
#define SB3 (SB2 + 64 * 128)
#define SB4 (SB3 + 64 * 128)
#define SB5 (SB4 + 128 * 128)
#define SB6 (SB5 + 128 * 128)

__device__ __forceinline__ void split4(float4 v, uint2& h, uint2& l) {
    uint32_t h0, l0, h1, l1;
    split2(v.x, v.y, h0, l0);
    split2(v.z, v.w, h1, l1);
    h = {h0, h1};
    l = {l0, l1};
}

__global__ void k_split7(const float* __restrict__ xdf, const float* __restrict__ xef,
                         const float* __restrict__ Wp1, const float* __restrict__ Wk,
                         const float* __restrict__ Wv,  const float* __restrict__ Wq,
                         const float* __restrict__ Wt)
{
    int e = (blockIdx.x * 256 + threadIdx.x) * 4;
    const float* src; __nv_bfloat16 *dh, *dl; int off;
    if      (e < SB0) { src = xdf; dh = g_dfh;  dl = g_dfl;  off = e; }
    else if (e < SB1) { src = xef; dh = g_eh;   dl = g_el;   off = e - SB0; }
    else if (e < SB2) { src = Wp1; dh = g_wp1h; dl = g_wp1l; off = e - SB1; }
    else if (e < SB3) { src = Wk;  dh = g_wkh;  dl = g_wkl;  off = e - SB2; }
    else if (e < SB4) { src = Wv;  dh = g_wvh;  dl = g_wvl;  off = e - SB3; }
    else if (e < SB5) { src = Wq;  dh = g_wqh;  dl = g_wql;  off = e - SB4; }
    else              { src = Wt;  dh = g_wth;  dl = g_wtl;  off = e - SB5; }
    float4 v = *reinterpret_cast<const float4*>(src + off);
    uint2 h, l;
    split4(v, h, l);
    *reinterpret_cast<uint2*>(dh + off) = h;
    *reinterpret_cast<uint2*>(dl + off) = l;
}

// ======================================================================
// Shared HMMA tile machinery (64x128 tile, 8 warps as 4 qw x 2 nw)
// ======================================================================
#define GOAH  0
#define GOAL  9216
#define GOBH  18432
#define GOBL  35840
#define GSTG  53248
#define GSMSZ (GSTG + 4096)

__device__ __forceinline__ void mma_tile64(uint32_t sbase,
                                           uint32_t bOffH, uint32_t bOffL,
                                           int qw, int nw, int lane,
                                           float acc[8][4])
{
    const int rA = lane & 15, cA = (lane >> 4) * 8;
    const int rV = ((lane >> 3) & 1) * 8 + (lane & 7);
    const int cV = ((lane >> 3) & 2) * 4;
#pragma unroll
    for (int kc = 0; kc < 4; ++kc) {
        uint32_t Aaddr = sbase + (uint32_t)((qw * 16 + rA) * 72 + kc * 16 + cA) * 2;
        uint32_t Ah4[4], Al4[4];
        ldsm4(Ah4, Aaddr + GOAH);
        ldsm4(Al4, Aaddr + GOAL);
#pragma unroll
        for (int nt2 = 0; nt2 < 4; ++nt2) {
            uint32_t ra = (uint32_t)((kc * 16 + rV) * 136 + nw * 64 + nt2 * 16 + cV) * 2;
            uint32_t Bh4[4], Bl4[4];
            ldsm4t(Bh4, sbase + bOffH + ra);
            ldsm4t(Bl4, sbase + bOffL + ra);
            float* a0 = acc[nt2 * 2];
            float* a1 = acc[nt2 * 2 + 1];
            mma16816(a0, Ah4, Bh4);  mma16816(a1, Ah4, Bh4 + 2);
            mma16816(a0, Ah4, Bl4);  mma16816(a1, Ah4, Bl4 + 2);
            mma16816(a0, Al4, Bh4);  mma16816(a1, Al4, Bh4 + 2);
        }
    }
}

// ======================================================================
// p1 gather-conv (unchanged winner)
// ======================================================================
__global__ __launch_bounds__(256) void k_p1_mma(const int* __restrict__ nbr)
{
    extern __shared__ char smr[];
    const uint32_t sbase = (uint32_t)__cvta_generic_to_shared(smr);
    const int tid = threadIdx.x;
    const int wid = tid >> 5, lane = tid & 31;
    const int qw = wid >> 1, nw = wid & 1;
    const int m0 = blockIdx.x * 64;

    float acc[8][4];
#pragma unroll
    for (int i = 0; i < 8; ++i)
#pragma unroll
        for (int j = 0; j < 4; ++j) acc[i][j] = 0.f;

    auto prefetch = [&](int k, int s) {
        uint32_t sb = sbase + s * GSTG;
#pragma unroll
        for (int i = 0; i < 2; ++i) {
            int idx = tid + i * 256;
            int r = idx >> 3, c = idx & 7;
            int gi = nbr[(m0 + r) * 27 + k];
            uint32_t so = (uint32_t)(r * 72 + c * 8) * 2;
            cpa16(sb + GOAH + so, g_dfh + (size_t)gi * DEC + c * 8);
            cpa16(sb + GOAL + so, g_dfl + (size_t)gi * DEC + c * 8);
        }
        const __nv_bfloat16* wh = g_wp1h + (size_t)k * 64 * 128;
        const __nv_bfloat16* wl = g_wp1l + (size_t)k * 64 * 128;
#pragma unroll
        for (int i = 0; i < 4; ++i) {
            int idx = tid + i * 256;
            int r = idx >> 4, c = idx & 15;
            uint32_t so = (uint32_t)(r * 136 + c * 8) * 2;
            cpa16(sb + GOBH + so, wh + r * 128 + c * 8);
            cpa16(sb + GOBL + so, wl + r * 128 + c * 8);
        }
        cpa_commit();
    };

    prefetch(0, 0);
    for (int k = 0; k < 27; ++k) {
        const int s = k & 1;
        if (k + 1 < 27) {
            prefetch(k + 1, s ^ 1);
            asm volatile("cp.async.wait_group 1;");
        } else {
            asm volatile("cp.async.wait_group 0;");
        }
        __syncthreads();
        mma_tile64(sbase + s * GSTG, GOBH, GOBL, qw, nw, lane, acc);
        __syncthreads();
    }

    const int g = lane >> 2, t = lane & 3;
    const int r0 = m0 + qw * 16 + g, r1 = r0 + 8;
#pragma unroll
    for (int nt = 0; nt < 8; ++nt) {
        int col = nw * 64 + nt * 8 + 2 * t;
        float2 v0 = {acc[nt][0], acc[nt][1]};
        float2 v1 = {acc[nt][2], acc[nt][3]};
        *reinterpret_cast<float2*>(g_xdec + (size_t)r0 * 128 + col) = v0;
        *reinterpret_cast<float2*>(g_xdec + (size_t)r1 * 128 + col) = v1;
        uint32_t h, l;
        split2(v0.x, v0.y, h, l);
        *reinterpret_cast<uint32_t*>(g_xdh + (size_t)r0 * 128 + col) = h;
        *reinterpret_cast<uint32_t*>(g_xdl + (size_t)r0 * 128 + col) = l;
        split2(v1.x, v1.y, h, l);
        *reinterpret_cast<uint32_t*>(g_xdh + (size_t)r1 * 128 + col) = h;
        *reinterpret_cast<uint32_t*>(g_xdl + (size_t)r1 * 128 + col) = l;
    }
}

// ======================================================================
// Fused K+V projection: K split-bf16, V plain fp16
// ======================================================================
#define KV_BKH 18432
#define KV_BKL (KV_BKH + 17408)
#define KV_BVH (KV_BKH + 34816)
#define KV_BVL (KV_BVH + 17408)
#define KVSMSZ (KV_BVH + 34816)

__global__ __launch_bounds__(256) void k_projKV()
{
    extern __shared__ char smr[];
    const uint32_t sbase = (uint32_t)__cvta_generic_to_shared(smr);
    const int tid = threadIdx.x;
    const int wid = tid >> 5, lane = tid & 31;
    const int qw = wid >> 1, nw = wid & 1;
    const int m0 = blockIdx.x * 64;

#pragma unroll
    for (int i = 0; i < 2; ++i) {
        int idx = tid + i * 256;
        int r = idx >> 3, c = idx & 7;
        size_t go = (size_t)(m0 + r) * DEC + c * 8;
        uint32_t so = (uint32_t)(r * 72 + c * 8) * 2;
        cpa16(sbase + GOAH + so, g_eh + go);
        cpa16(sbase + GOAL + so, g_el + go);
    }
#pragma unroll
    for (int i = 0; i < 4; ++i) {
        int idx = tid + i * 256;
        int r = idx >> 4, c = idx & 15;
        size_t go = (size_t)r * 128 + c * 8;
        uint32_t so = (uint32_t)(r * 136 + c * 8) * 2;
        cpa16(sbase + KV_BKH + so, g_wkh + go);
        cpa16(sbase + KV_BKL + so, g_wkl + go);
        cpa16(sbase + KV_BVH + so, g_wvh + go);
        cpa16(sbase + KV_BVL + so, g_wvl + go);
    }
    cpa_commit();
    asm volatile("cp.async.wait_group 0;");
    __syncthreads();

    float accK[8][4], accV[8][4];
#pragma unroll
    for (int i = 0; i < 8; ++i)
#pragma unroll
        for (int j = 0; j < 4; ++j) { accK[i][j] = 0.f; accV[i][j] = 0.f; }

    mma_tile64(sbase, KV_BKH, KV_BKL, qw, nw, lane, accK);
    mma_tile64(sbase, KV_BVH, KV_BVL, qw, nw, lane, accV);

    const int g = lane >> 2, t = lane & 3;
    const int r0 = m0 + qw * 16 + g, r1 = r0 + 8;
#pragma unroll
    for (int nt = 0; nt < 8; ++nt) {
        int col = nw * 64 + nt * 8 + 2 * t;
        uint32_t h, l;
        split2(accK[nt][0], accK[nt][1], h, l);
        *reinterpret_cast<uint32_t*>(g_kh + (size_t)r0 * 128 + col) = h;
        *reinterpret_cast<uint32_t*>(g_kl + (size_t)r0 * 128 + col) = l;
        split2(accK[nt][2], accK[nt][3], h, l);
        *reinterpret_cast<uint32_t*>(g_kh + (size_t)r1 * 128 + col) = h;
        *reinterpret_cast<uint32_t*>(g_kl + (size_t)r1 * 128 + col) = l;
        *reinterpret_cast<uint32_t*>(g_vh + (size_t)r0 * 128 + col) =
            packh(accV[nt][0], accV[nt][1]);
        *reinterpret_cast<uint32_t*>(g_vh + (size_t)r1 * 128 + col) =
            packh(accV[nt][2], accV[nt][3]);
    }
}

// ======================================================================
// Generic split-bf16 HMMA GEMM (+ split out / BN stats) — unchanged winner
// ======================================================================
template <int KA, bool SPLIT, bool STATS>
__global__ __launch_bounds__(256) void k_proj(const __nv_bfloat16* __restrict__ Ahg,
                                              const __nv_bfloat16* __restrict__ Alg,
                                              const __nv_bfloat16* __restrict__ Bhg,
                                              const __nv_bfloat16* __restrict__ Blg,
                                              __nv_bfloat16* __restrict__ Ch,
                                              __nv_bfloat16* __restrict__ Cl,
                                              float* __restrict__ Cf)
{
    extern __shared__ char smr[];
    const uint32_t sbase = (uint32_t)__cvta_generic_to_shared(smr);
    const int tid = threadIdx.x;
    const int wid = tid >> 5, lane = tid & 31;
    const int qw = wid >> 1, nw = wid & 1;
    const int m0 = blockIdx.x * 64;

    float acc[8][4];
#pragma unroll
    for (int i = 0; i < 8; ++i)
#pragma unroll
        for (int j = 0; j < 4; ++j) acc[i][j] = 0.f;

#pragma unroll
    for (int kb = 0; kb < KA / 64; ++kb) {
        __syncthreads();
#pragma unroll
        for (int i = 0; i < 2; ++i) {
            int idx = tid + i * 256;
            int r = idx >> 3, c = idx & 7;
            size_t go = (size_t)(m0 + r) * KA + kb * 64 + c * 8;
            uint32_t so = (uint32_t)(r * 72 + c * 8) * 2;
            cpa16(sbase + GOAH + so, Ahg + go);
            cpa16(sbase + GOAL + so, Alg + go);
        }
#pragma unroll
        for (int i = 0; i < 4; ++i) {
            int idx = tid + i * 256;
            int r = idx >> 4, c = idx & 15;
            size_t go = (size_t)(kb * 64 + r) * 128 + c * 8;
            uint32_t so = (uint32_t)(r * 136 + c * 8) * 2;
            cpa16(sbase + GOBH + so, Bhg + go);
            cpa16(sbase + GOBL + so, Blg + go);
        }
        cpa_commit();
        asm volatile("cp.async.wait_group 0;");
        __syncthreads();
        mma_tile64(sbase, GOBH, GOBL, qw, nw, lane, acc);
    }

    const int g = lane >> 2, t = lane & 3;
    const int r0 = m0 + qw * 16 + g, r1 = r0 + 8;
#pragma unroll
    for (int nt = 0; nt < 8; ++nt) {
        int col = nw * 64 + nt * 8 + 2 * t;
        if (SPLIT) {
            uint32_t h, l;
            split2(acc[nt][0], acc[nt][1], h, l);
            *reinterpret_cast<uint32_t*>(Ch + (size_t)r0 * 128 + col) = h;
            *reinterpret_cast<uint32_t*>(Cl + (size_t)r0 * 128 + col) = l;
            split2(acc[nt][2], acc[nt][3], h, l);
            *reinterpret_cast<uint32_t*>(Ch + (size_t)r1 * 128 + col) = h;
            *reinterpret_cast<uint32_t*>(Cl + (size_t)r1 * 128 + col) = l;
        } else {
            float2 v0 = {acc[nt][0], acc[nt][1]};
            float2 v1 = {acc[nt][2], acc[nt][3]};
            *reinterpret_cast<float2*>(Cf + (size_t)r0 * 128 + col) = v0;
            *reinterpret_cast<float2*>(Cf + (size_t)r1 * 128 + col) = v1;
        }
    }

    if (STATS) {
        float* sS = reinterpret_cast<float*>(smr);
        float* sQ = reinterpret_cast<float*>(smr + 2048);
        __syncthreads();
        float cs[8][2], cq[8][2];
#pragma unroll
        for (int nt = 0; nt < 8; ++nt) {
            cs[nt][0] = acc[nt][0] + acc[nt][2];
            cs[nt][1] = acc[nt][1] + acc[nt][3];
            cq[nt][0] = acc[nt][0] * acc[nt][0] + acc[nt][2] * acc[nt][2];
            cq[nt][1] = acc[nt][1] * acc[nt][1] + acc[nt][3] * acc[nt][3];
        }
#pragma unroll
        for (int off = 4; off < 32; off <<= 1) {
#pragma unroll
            for (int nt = 0; nt < 8; ++nt) {
                cs[nt][0] += __shfl_xor_sync(0xffffffffu, cs[nt][0], off);
                cs[nt][1] += __shfl_xor_sync(0xffffffffu, cs[nt][1], off);
                cq[nt][0] += __shfl_xor_sync(0xffffffffu, cq[nt][0], off);
                cq[nt][1] += __shfl_xor_sync(0xffffffffu, cq[nt][1], off);
            }
        }
        if (lane < 4) {
#pragma unroll
            for (int nt = 0; nt < 8; ++nt) {
                int col = nw * 64 + nt * 8 + 2 * lane;
                sS[qw * 128 + col]     = cs[nt][0];
                sS[qw * 128 + col + 1] = cs[nt][1];
                sQ[qw * 128 + col]     = cq[nt][0];
                sQ[qw * 128 + col + 1] = cq[nt][1];
            }
        }
        __syncthreads();
        if (tid < 128) {
            float s = sS[tid] + sS[128 + tid] + sS[256 + tid] + sS[384 + tid];
            float q = sQ[tid] + sQ[128 + tid] + sQ[256 + tid] + sQ[384 + tid];
            g_psum[blockIdx.x * 128 + tid] = s;
            g_psq [blockIdx.x * 128 + tid] = q;
        }
    }
}

// ======================================================================
// Flash attention v4: cross-iteration software pipeline.
// 128 q-rows/block, 256 threads, kv-tile 64, 3-stage cp.async ring.
// Order per iter: softmax(j) -> [wait j+1; prefetch j+2; S(j+1)] -> PV(j).
// stage = KH | KL | VH (3 x 17408 B), 3 stages.
// ======================================================================
#define STG   17408
#define SSTAGE (3 * STG)              // 52224 per stage
#define ASMSZ2 (3 * SSTAGE)           // 156672 total

__global__ __launch_bounds__(256, 1) void k_attn()
{
    extern __shared__ char smr[];
    const uint32_t sbase = (uint32_t)__cvta_generic_to_shared(smr);

    const int tid  = threadIdx.x;
    const int w    = tid >> 5, lane = tid & 31;
    const int g    = lane >> 2, t = lane & 3;
    const int b    = blockIdx.y;
    const size_t qrow0 = (size_t)b * NQB + blockIdx.x * 128;

    const int rA = lane & 15;
    const int cA = (lane >> 4) * 8;
    const int rB = ((lane >> 3) & 2) * 4 + (lane & 7);
    const int cB = ((lane >> 3) & 1) * 8;
    const int rV = ((lane >> 3) & 1) * 8 + (lane & 7);
    const int cV = ((lane >> 3) & 2) * 4;

    // ---- stage Q, load register A-fragments ----
    uint32_t Qh[8][4], Ql[8][4];
    {
        const __nv_bfloat16* qh = g_qh + qrow0 * 128;
        const __nv_bfloat16* ql = g_ql + qrow0 * 128;
#pragma unroll
        for (int i = 0; i < 8; ++i) {
            int idx = tid + i * 256;
            int r = idx >> 4, c = idx & 15;
            uint32_t so = (uint32_t)(r * 136 + c * 8) * 2;
            cpa16(sbase + so,         qh + (size_t)r * 128 + c * 8);
            cpa16(sbase + 34816 + so, ql + (size_t)r * 128 + c * 8);
        }
        cpa_commit();
        asm volatile("cp.async.wait_group 0;");
        __syncthreads();
#pragma unroll
        for (int ch = 0; ch < 8; ++ch) {
            uint32_t Aaddr = sbase + (uint32_t)((w * 16 + rA) * 136 + ch * 16 + cA) * 2;
            ldsm4(Qh[ch], Aaddr);
            ldsm4(Ql[ch], Aaddr + 34816);
        }
        __syncthreads();
    }

    float O[16][4];
#pragma unroll
    for (int i = 0; i < 16; ++i)
#pragma unroll
        for (int j = 0; j < 4; ++j) O[i][j] = 0.f;
    float m0r = -1e30f, m1r = -1e30f, l0 = 0.f, l1 = 0.f;

    const size_t kvbase = (size_t)b * NKB * 128;
    auto prefetch = [&](int jt) {
        size_t base = kvbase + (size_t)jt * 64 * 128;
        uint32_t sb = sbase + (uint32_t)(jt % 3) * SSTAGE;
#pragma unroll
        for (int i = 0; i < 12; ++i) {
            int arr = i >> 2;                    // 0:KH 1:KL 2:VH
            int idx = tid + (i & 3) * 256;
            int r = idx >> 4, c = idx & 15;
            uint32_t so = sb + arr * STG + (uint32_t)(r * 136 + c * 8) * 2;
            size_t eo = base + (size_t)r * 128 + c * 8;
            const void* src;
            if      (arr == 0) src = g_kh + eo;
            else if (arr == 1) src = g_kl + eo;
            else               src = g_vh + eo;
            cpa16(so, src);
        }
        cpa_commit();
    };

    auto computeS = [&](float (&sAn)[8][4], int jn) {
        const uint32_t KHb = sbase + (uint32_t)(jn % 3) * SSTAGE;
        const uint32_t KLb = KHb + STG;
#pragma unroll
        for (int i = 0; i < 8; ++i)
#pragma unroll
            for (int j = 0; j < 4; ++j) sAn[i][j] = 0.f;
#pragma unroll
        for (int ch = 0; ch < 8; ++ch) {
            uint32_t col = (uint32_t)(ch * 16 + cB) * 2;
#pragma unroll
            for (int r4 = 0; r4 < 4; ++r4) {
                uint32_t ra = (uint32_t)((r4 * 16 + rB) * 136) * 2 + col;
                uint32_t bh[4], bl[4];
                ldsm4(bh, KHb + ra);
                ldsm4(bl, KLb + ra);
                float* s0 = sAn[r4 * 2];
                float* s1 = sAn[r4 * 2 + 1];
                mma16816(s0, Qh[ch], bh);      mma16816(s1, Qh[ch], bh + 2);
                mma16816(s0, Qh[ch], bl);      mma16816(s1, Qh[ch], bl + 2);
                mma16816(s0, Ql[ch], bh);      mma16816(s1, Ql[ch], bh + 2);
            }
        }
    };

    const int NIT = NKB / 64;                    // 64

    auto step = [&](float (&sAc)[8][4], float (&sAn)[8][4], int jt) {
        // ---- softmax over full 64 kv (depends on S(jt), issued last iter) ----
        float rm0 = sAc[0][0], rm1 = sAc[0][2];
#pragma unroll
        for (int nt = 0; nt < 8; ++nt) {
            rm0 = fmaxf(rm0, fmaxf(sAc[nt][0], sAc[nt][1]));
            rm1 = fmaxf(rm1, fmaxf(sAc[nt][2], sAc[nt][3]));
        }
        rm0 = fmaxf(rm0, __shfl_xor_sync(0xffffffffu, rm0, 1));
        rm0 = fmaxf(rm0, __shfl_xor_sync(0xffffffffu, rm0, 2));
        rm1 = fmaxf(rm1, __shfl_xor_sync(0xffffffffu, rm1, 1));
        rm1 = fmaxf(rm1, __shfl_xor_sync(0xffffffffu, rm1, 2));
        float mn0 = fmaxf(m0r, rm0);
        float mn1 = fmaxf(m1r, rm1);
        float sc0 = __expf(m0r - mn0);
        float sc1 = __expf(m1r - mn1);

        float p[8][4];
        float ls0 = 0.f, ls1 = 0.f;
#pragma unroll
        for (int nt = 0; nt < 8; ++nt) {
            p[nt][0] = __expf(sAc[nt][0] - mn0);
            p[nt][1] = __expf(sAc[nt][1] - mn0);
            p[nt][2] = __expf(sAc[nt][2] - mn1);
            p[nt][3] = __expf(sAc[nt][3] - mn1);
            ls0 += p[nt][0] + p[nt][1];
            ls1 += p[nt][2] + p[nt][3];
        }
        ls0 += __shfl_xor_sync(0xffffffffu, ls0, 1);
        ls0 += __shfl_xor_sync(0xffffffffu, ls0, 2);
        ls1 += __shfl_xor_sync(0xffffffffu, ls1, 1);
        ls1 += __shfl_xor_sync(0xffffffffu, ls1, 2);
        l0 = l0 * sc0 + ls0;
        l1 = l1 * sc1 + ls1;
        m0r = mn0; m1r = mn1;

#pragma unroll
        for (int nt = 0; nt < 16; ++nt) {
            O[nt][0] *= sc0; O[nt][1] *= sc0;
            O[nt][2] *= sc1; O[nt][3] *= sc1;
        }

        // P as fp16 A-fragments (4 k-chunks of 16)
        uint32_t Ph[4][4];
#pragma unroll
        for (int c = 0; c < 4; ++c) {
            Ph[c][0] = packh(p[2 * c][0],     p[2 * c][1]);
            Ph[c][1] = packh(p[2 * c][2],     p[2 * c][3]);
            Ph[c][2] = packh(p[2 * c + 1][0], p[2 * c + 1][1]);
            Ph[c][3] = packh(p[2 * c + 1][2], p[2 * c + 1][3]);
        }

        // ---- pipeline: S for tile jt+1 (fills tensor pipe while softmax result settles) ----
        if (jt + 1 < NIT) {
            asm volatile("cp.async.wait_group 0;");
            __syncthreads();
            if (jt + 2 < NIT) prefetch(jt + 2);
            computeS(sAn, jt + 1);
        }

        // ---- PV(jt) ----
        const uint32_t VHb = sbase + (uint32_t)(jt % 3) * SSTAGE + 2 * STG;
#pragma unroll
        for (int kc = 0; kc < 4; ++kc) {
#pragma unroll
            for (int dp = 0; dp < 8; ++dp) {
                uint32_t ra = (uint32_t)((kc * 16 + rV) * 136 + dp * 16 + cV) * 2;
                uint32_t vh[4];
                ldsm4t(vh, VHb + ra);
                mma16816h(O[dp * 2],     Ph[kc], vh);
                mma16816h(O[dp * 2 + 1], Ph[kc], vh + 2);
            }
        }
    };

    // ---- preamble: two tiles in flight, S(0) in registers ----
    prefetch(0);
    prefetch(1);
    asm volatile("cp.async.wait_group 1;");
    __syncthreads();

    float sA0[8][4], sA1[8][4];
    computeS(sA0, 0);

    for (int jt = 0; jt < NIT; jt += 2) {
        step(sA0, sA1, jt);
        step(sA1, sA0, jt + 1);
    }

    // ---- epilogue: normalize, split, store ----
    float inv0 = 1.f / l0, inv1 = 1.f / l1;
    size_t out0 = (qrow0 + w * 16 + g) * 128;
    size_t out1 = (qrow0 + w * 16 + g + 8) * 128;
#pragma unroll
    for (int nt = 0; nt < 16; ++nt) {
        int c0 = nt * 8 + 2 * t;
        uint32_t h, l;
        split2(O[nt][0] * inv0, O[nt][1] * inv0, h, l);
        *reinterpret_cast<uint32_t*>(g_xrh + out0 + c0) = h;
        *reinterpret_cast<uint32_t*>(g_xrl + out0 + c0) = l;
        split2(O[nt][2] * inv1, O[nt][3] * inv1, h, l);
        *reinterpret_cast<uint32_t*>(g_xrh + out1 + c0) = h;
        *reinterpret_cast<uint32_t*>(g_xrl + out1 + c0) = l;
    }
}

// ======================================================================
// BN finalize + epilogue
// ======================================================================
__global__ void k_stats()
{
    int f = threadIdx.x;
    float s = 0.f, q = 0.f;
    for (int b = 0; b < NQ / 64; ++b) {
        s += g_psum[b * 128 + f];
        q += g_psq [b * 128 + f];
    }
    float mean = s * (1.f / NQ);
    float var  = q * (1.f / NQ) - mean * mean;
    g_mean[f] = mean;
    g_rstd[f] = rsqrtf(var + BN_EPS);
}

__global__ void k_final(const float* __restrict__ gamma, const float* __restrict__ beta,
                        float* __restrict__ out)
{
    int idx = blockIdx.x * 256 + threadIdx.x;
    int f   = (idx & 31) * 4;
    float4 tv = *reinterpret_cast<const float4*>(g_t    + (size_t)idx * 4);
    float4 xd = *reinterpret_cast<const float4*>(g_xdec + (size_t)idx * 4);
    float4 r;
    r.x = xd.x + (tv.x - g_mean[f + 0]) * g_rstd[f + 0] * gamma[f + 0] + beta[f + 0];
    r.y = xd.y + (tv.y - g_mean[f + 1]) * g_rstd[f + 1] * gamma[f + 1] + beta[f + 1];
    r.z = xd.z + (tv.z - g_mean[f + 2]) * g_rstd[f + 2] * gamma[f + 2] + beta[f + 2];
    r.w = xd.w + (tv.w - g_mean[f + 3]) * g_rstd[f + 3] * gamma[f + 3] + beta[f + 3];
    *reinterpret_cast<float4*>(out + (size_t)idx * 4) = r;
}

// ======================================================================
extern "C" void kernel_launch(void* const* d_in, const int* in_sizes, int n_in,
                              void* d_out, int out_size)
{
    const float* xdec_f = (const float*)d_in[0];
    const float* xenc_f = (const float*)d_in[1];
    const int*   nbr    = (const int*)  d_in[2];
    const float* Wp1    = (const float*)d_in[3];
    const float* Wq     = (const float*)d_in[4];
    const float* Wk     = (const float*)d_in[5];
    const float* Wv     = (const float*)d_in[6];
    const float* Wt     = (const float*)d_in[7];
    const float* gamma  = (const float*)d_in[8];
    const float* beta   = (const float*)d_in[9];
    float* out = (float*)d_out;

    __nv_bfloat16 *p_xdh, *p_xdl, *p_xrh, *p_xrl;
    __nv_bfloat16 *p_wqh, *p_wql, *p_wth, *p_wtl;
    __nv_bfloat16 *p_qh, *p_ql;
    float *p_t;
    cudaGetSymbolAddress((void**)&p_xdh, g_xdh);  cudaGetSymbolAddress((void**)&p_xdl, g_xdl);
    cudaGetSymbolAddress((void**)&p_xrh, g_xrh);  cudaGetSymbolAddress((void**)&p_xrl, g_xrl);
    cudaGetSymbolAddress((void**)&p_wqh, g_wqh);  cudaGetSymbolAddress((void**)&p_wql, g_wql);
    cudaGetSymbolAddress((void**)&p_wth, g_wth);  cudaGetSymbolAddress((void**)&p_wtl, g_wtl);
    cudaGetSymbolAddress((void**)&p_qh,  g_qh);   cudaGetSymbolAddress((void**)&p_ql,  g_ql);
    cudaGetSymbolAddress((void**)&p_t,   g_t);

    cudaFuncSetAttribute(k_p1_mma,  cudaFuncAttributeMaxDynamicSharedMemorySize, 2 * GSTG);
    cudaFuncSetAttribute(k_projKV,  cudaFuncAttributeMaxDynamicSharedMemorySize, KVSMSZ);
    cudaFuncSetAttribute(k_proj<128, true,  false>, cudaFuncAttributeMaxDynamicSharedMemorySize, GSMSZ);
    cudaFuncSetAttribute(k_proj<128, false, true >, cudaFuncAttributeMaxDynamicSharedMemorySize, GSMSZ);
    cudaFuncSetAttribute(k_attn,    cudaFuncAttributeMaxDynamicSharedMemorySize, ASMSZ2);

    k_split7<<<SB6 / 1024, 256>>>(xdec_f, xenc_f, Wp1, Wk, Wv, Wq, Wt);
    k_p1_mma<<<NQ / 64, 256, 2 * GSTG>>>(nbr);
    k_projKV<<<NKV / 64, 256, KVSMSZ>>>();
    k_proj<128, true,  false><<<NQ / 64, 256, GSMSZ>>>(p_xdh, p_xdl, p_wqh, p_wql, p_qh, p_ql, nullptr);
    k_attn<<<dim3(NQB / 128, NBATCH), 256, ASMSZ2>>>();
    k_proj<128, false, true ><<<NQ / 64, 256, GSMSZ>>>(p_xrh, p_xrl, p_wth, p_wtl, nullptr, nullptr, p_t);
    k_stats<<<1, 128>>>();
    k_final<<<(NQ * NF / 4) / 256, 256>>>(gamma, beta, out);
}